// round 3
// baseline (speedup 1.0000x reference)
#include <cuda_runtime.h>
#include <cstdint>

#define WV 14
#define WP 16          // padded width in global buffers (cols 0,15 zero)
#define P  20          // smem row pitch (floats), multiple of 4
#define B_TOTAL 2048

__device__ float g_bufA[(size_t)B_TOTAL * 32768];
__device__ float g_bufB[(size_t)B_TOTAL * 32768];
// Transposed weights [ci*9+k][co]: w1T @0, w2T @4096, w3T @81920
__device__ float g_wT[4096 + 73728 + 294912 + 1024];

typedef unsigned long long ull;

__device__ __forceinline__ ull pack2(float x) {
    ull r;
    asm("mov.b64 %0, {%1, %1};" : "=l"(r) : "f"(x));
    return r;
}
__device__ __forceinline__ void fma2(ull &acc, ull a, ull b) {
    asm("fma.rn.f32x2 %0, %1, %2, %0;" : "+l"(acc) : "l"(a), "l"(b));
}
__device__ __forceinline__ float2 unpack2(ull v) {
    float2 r;
    asm("mov.b64 {%0, %1}, %2;" : "=f"(r.x), "=f"(r.y) : "l"(v));
    return r;
}

// Weight transpose: w[co][ci][3][3] -> wT[ci*9+k][co]
__global__ void transpose_w_kernel(const float* __restrict__ w,
                                   float* __restrict__ wT,
                                   int CIN, int COUT)
{
    int i = blockIdx.x * 256 + threadIdx.x;
    int total = COUT * CIN * 9;
    if (i >= total) return;
    int co = i / (CIN * 9);
    int r  = i % (CIN * 9);
    wT[r * COUT + co] = w[i];
}

// =====================================================================
// Fused conv(3x3, stride (2,1), pad (1,1)) + BN + ReLU.  1024 threads.
// One CTA per sample. Whole input slab in smem, rows shifted +1 with
// row 0 = zeros (pad).  Thread = (wh, h, cp): 4 output channels
// co0=4cp, 7 width outputs (w_global = 7*wh + w).
// Requires 2 * HOUT * (COUT/4) == 1024.
// =====================================================================
template<int CIN, int COUT, int HIN, int HOUT, int CI_BLK, bool FIRST>
__global__ void __launch_bounds__(1024, 1)
conv_v3(const float* __restrict__ in0,
        const float* __restrict__ in1,    // sigmas when FIRST
        const float* __restrict__ wT,     // [CIN*9][COUT]
        const float* __restrict__ gam,
        const float* __restrict__ bet,
        const float* __restrict__ mu,
        const float* __restrict__ var,
        float* __restrict__ out)          // [B][COUT][HOUT][WP]
{
    constexpr int ROWS    = HIN + 1;
    constexpr int IN_SM   = CIN * ROWS * P;
    constexpr int W_ELEMS = CI_BLK * 9 * COUT;
    constexpr int CP4     = COUT / 4;

    extern __shared__ float smem[];
    float* s_in = smem;                 // [CIN][ROWS][P]
    float* s_w  = smem + IN_SM;         // [CI_BLK*9][COUT]

    const int b   = blockIdx.x;
    const int tid = threadIdx.x;

    // zero whole input slab (covers pad row/cols), then fill
    {
        float4 z = make_float4(0.f, 0.f, 0.f, 0.f);
        for (int i = tid * 4; i < IN_SM; i += 4096)
            *reinterpret_cast<float4*>(s_in + i) = z;
    }
    __syncthreads();

    if (FIRST) {
        // ch0 = x, ch1 = 10*sigmas; data cols 1..14, rows 1..HIN
        for (int i = tid; i < HIN * WV; i += 1024) {
            int f = i / WV, k = i % WV;
            s_in[(f + 1) * P + k + 1]              = in0[(size_t)b * (HIN * WV) + i];
            s_in[(ROWS + f + 1) * P + k + 1]       = in1[(size_t)b * (HIN * WV) + i] * 10.0f;
        }
    } else {
        const float* gin = in0 + (size_t)b * (CIN * HIN * WP);
        for (int e = tid; e < CIN * HIN * 4; e += 1024) {
            int i  = e * 4;
            int ci = i / (HIN * WP);
            int rm = i % (HIN * WP);
            int r  = rm >> 4;
            int c  = rm & 15;
            *reinterpret_cast<float4*>(s_in + ci * (ROWS * P) + (r + 1) * P + c) =
                *reinterpret_cast<const float4*>(gin + i);
        }
    }

    const int wh  = tid >> 9;           // warp-uniform
    const int rem = tid & 511;
    const int h   = rem / CP4;          // warp-uniform (CP4 >= 16)
    const int cp  = rem % CP4;
    const int co0 = cp * 4;

    ull accA[7], accB[7];
    #pragma unroll
    for (int w = 0; w < 7; w++) { accA[w] = 0ull; accB[w] = 0ull; }

    for (int ci0 = 0; ci0 < CIN; ci0 += CI_BLK) {
        __syncthreads();
        {   // coalesced weight staging from pre-transposed layout
            const float4* src =
                reinterpret_cast<const float4*>(wT + (size_t)ci0 * 9 * COUT);
            float4* dst = reinterpret_cast<float4*>(s_w);
            for (int e = tid; e < W_ELEMS / 4; e += 1024) dst[e] = src[e];
        }
        __syncthreads();

        for (int ci = 0; ci < CI_BLK; ci++) {
            const float* ib = s_in + (ci0 + ci) * (ROWS * P) + 4 * wh;
            const float* wb = s_w + ci * 9 * COUT + co0;
            #pragma unroll
            for (int kh = 0; kh < 3; kh++) {
                const float4* row4 =
                    reinterpret_cast<const float4*>(ib + (2 * h + kh) * P);
                float4 q0 = row4[0], q1 = row4[1], q2 = row4[2];
                ull pv[9];
                if (wh == 0) {
                    pv[0] = pack2(q0.x); pv[1] = pack2(q0.y); pv[2] = pack2(q0.z);
                    pv[3] = pack2(q0.w); pv[4] = pack2(q1.x); pv[5] = pack2(q1.y);
                    pv[6] = pack2(q1.z); pv[7] = pack2(q1.w); pv[8] = pack2(q2.x);
                } else {
                    pv[0] = pack2(q0.w); pv[1] = pack2(q1.x); pv[2] = pack2(q1.y);
                    pv[3] = pack2(q1.z); pv[4] = pack2(q1.w); pv[5] = pack2(q2.x);
                    pv[6] = pack2(q2.y); pv[7] = pack2(q2.z); pv[8] = pack2(q2.w);
                }
                #pragma unroll
                for (int kw = 0; kw < 3; kw++) {
                    ulonglong2 wp = *reinterpret_cast<const ulonglong2*>(
                        wb + (kh * 3 + kw) * COUT);
                    #pragma unroll
                    for (int w = 0; w < 7; w++) {
                        fma2(accA[w], pv[kw + w], wp.x);
                        fma2(accB[w], pv[kw + w], wp.y);
                    }
                }
            }
        }
    }

    // BN(eval) + ReLU epilogue: 4 channels x 7 width outputs
    float4 g4 = *reinterpret_cast<const float4*>(gam + co0);
    float4 b4 = *reinterpret_cast<const float4*>(bet + co0);
    float4 m4 = *reinterpret_cast<const float4*>(mu  + co0);
    float4 v4 = *reinterpret_cast<const float4*>(var + co0);
    float sc0 = g4.x * rsqrtf(v4.x + 1e-5f), sh0 = b4.x - m4.x * sc0;
    float sc1 = g4.y * rsqrtf(v4.y + 1e-5f), sh1 = b4.y - m4.y * sc1;
    float sc2 = g4.z * rsqrtf(v4.z + 1e-5f), sh2 = b4.z - m4.z * sc2;
    float sc3 = g4.w * rsqrtf(v4.w + 1e-5f), sh3 = b4.w - m4.w * sc3;

    float* r0 = out + (size_t)b * (COUT * HOUT * WP)
                    + (size_t)co0 * (HOUT * WP) + h * WP;
    float* r1 = r0 + HOUT * WP;
    float* r2 = r1 + HOUT * WP;
    float* r3 = r2 + HOUT * WP;
    int pc = wh ? (WV + 1) : 0;     // pad column this thread owns
    r0[pc] = 0.f; r1[pc] = 0.f; r2[pc] = 0.f; r3[pc] = 0.f;
    const int cbase = 1 + 7 * wh;
    #pragma unroll
    for (int w = 0; w < 7; w++) {
        float2 a = unpack2(accA[w]);
        float2 c = unpack2(accB[w]);
        r0[cbase + w] = fmaxf(fmaf(a.x, sc0, sh0), 0.f);
        r1[cbase + w] = fmaxf(fmaf(a.y, sc1, sh1), 0.f);
        r2[cbase + w] = fmaxf(fmaf(c.x, sc2, sh2), 0.f);
        r3[cbase + w] = fmaxf(fmaf(c.y, sc3, sh3), 0.f);
    }
}

// =====================================================================
// conv4: temporal merge (8,1), fused transpose. 2 warps/sample.
// =====================================================================
__global__ void __launch_bounds__(256)
conv4_kernel_v2(const float* __restrict__ in,   // [B][256][8][WP]
                const float* __restrict__ w4,   // [2][256][8][1]
                float* __restrict__ out)        // [B][14][2]
{
    __shared__ float part[8][28];
    const int warp = threadIdx.x >> 5;
    const int lane = threadIdx.x & 31;
    const int b    = blockIdx.x * 4 + (warp >> 1);
    const int half = warp & 1;

    const float* base = in + (size_t)b * 32768;
    float acc0[WV], acc1[WV];
    #pragma unroll
    for (int w = 0; w < WV; w++) { acc0[w] = 0.f; acc1[w] = 0.f; }

    const int ci_lo = 128 * half;
    for (int ci = ci_lo + lane; ci < ci_lo + 128; ci += 32) {
        const float* prow  = base + ci * (8 * WP);
        const float* wrow0 = w4 + ci * 8;
        const float* wrow1 = w4 + 2048 + ci * 8;
        #pragma unroll
        for (int kh = 0; kh < 8; kh++) {
            float w0 = wrow0[kh], w1 = wrow1[kh];
            const float4* r4 = reinterpret_cast<const float4*>(prow + kh * WP);
            float4 q0 = r4[0], q1 = r4[1], q2 = r4[2], q3 = r4[3];
            float v[16] = {q0.x,q0.y,q0.z,q0.w, q1.x,q1.y,q1.z,q1.w,
                           q2.x,q2.y,q2.z,q2.w, q3.x,q3.y,q3.z,q3.w};
            #pragma unroll
            for (int w = 0; w < WV; w++) {
                acc0[w] = fmaf(v[w + 1], w0, acc0[w]);
                acc1[w] = fmaf(v[w + 1], w1, acc1[w]);
            }
        }
    }
    #pragma unroll
    for (int off = 16; off > 0; off >>= 1) {
        #pragma unroll
        for (int w = 0; w < WV; w++) {
            acc0[w] += __shfl_down_sync(0xffffffffu, acc0[w], off);
            acc1[w] += __shfl_down_sync(0xffffffffu, acc1[w], off);
        }
    }
    if (lane == 0) {
        #pragma unroll
        for (int w = 0; w < WV; w++) {
            part[warp][w]      = acc0[w];
            part[warp][14 + w] = acc1[w];
        }
    }
    __syncthreads();
    if (threadIdx.x < 112) {
        int s = threadIdx.x / 28, j = threadIdx.x % 28;
        float v = part[2 * s][j] + part[2 * s + 1][j];
        int bb = blockIdx.x * 4 + s;
        int c = j / 14, w = j % 14;
        out[(size_t)bb * 28 + w * 2 + c] = v;
    }
}

extern "C" void kernel_launch(void* const* d_in, const int* in_sizes, int n_in,
                              void* d_out, int out_size)
{
    (void)n_in; (void)out_size;
    const float* x   = (const float*)d_in[0];
    const float* sig = (const float*)d_in[1];
    const float* w1  = (const float*)d_in[2];
    const float *w2, *w3, *w4;
    const float *g1,*b1,*m1,*v1,*g2,*b2,*m2,*v2,*g3,*b3,*m3,*v3;

    if (in_sizes[3] == 73728) {
        w2=(const float*)d_in[3];  w3=(const float*)d_in[4];  w4=(const float*)d_in[5];
        g1=(const float*)d_in[6];  b1=(const float*)d_in[7];  m1=(const float*)d_in[8];  v1=(const float*)d_in[9];
        g2=(const float*)d_in[10]; b2=(const float*)d_in[11]; m2=(const float*)d_in[12]; v2=(const float*)d_in[13];
        g3=(const float*)d_in[14]; b3=(const float*)d_in[15]; m3=(const float*)d_in[16]; v3=(const float*)d_in[17];
    } else {
        g1=(const float*)d_in[3];  b1=(const float*)d_in[4];  m1=(const float*)d_in[5];  v1=(const float*)d_in[6];
        w2=(const float*)d_in[7];
        g2=(const float*)d_in[8];  b2=(const float*)d_in[9];  m2=(const float*)d_in[10]; v2=(const float*)d_in[11];
        w3=(const float*)d_in[12];
        g3=(const float*)d_in[13]; b3=(const float*)d_in[14]; m3=(const float*)d_in[15]; v3=(const float*)d_in[16];
        w4=(const float*)d_in[17];
    }

    float *bufA = nullptr, *bufB = nullptr, *wT = nullptr;
    cudaGetSymbolAddress((void**)&bufA, g_bufA);
    cudaGetSymbolAddress((void**)&bufB, g_bufB);
    cudaGetSymbolAddress((void**)&wT,   g_wT);
    float* w1T = wT;
    float* w2T = wT + 4096;
    float* w3T = wT + 81920;

    transpose_w_kernel<<<(64 * 2 * 9 + 255) / 256, 256>>>(w1, w1T, 2, 64);
    transpose_w_kernel<<<(128 * 64 * 9 + 255) / 256, 256>>>(w2, w2T, 64, 128);
    transpose_w_kernel<<<(256 * 128 * 9 + 255) / 256, 256>>>(w3, w3T, 128, 256);

    const int smem1 = (2   * 65 * P + 2 * 9 * 64)  * 4;   //  15008 B
    const int smem2 = (64  * 33 * P + 8 * 9 * 128) * 4;   // 205824 B
    const int smem3 = (128 * 17 * P + 4 * 9 * 256) * 4;   // 210944 B

    cudaFuncSetAttribute(conv_v3<64,128,32,16,8,false>,
                         cudaFuncAttributeMaxDynamicSharedMemorySize, smem2);
    cudaFuncSetAttribute(conv_v3<128,256,16,8,4,false>,
                         cudaFuncAttributeMaxDynamicSharedMemorySize, smem3);

    conv_v3<2,64,64,32,2,true><<<B_TOTAL, 1024, smem1>>>(
        x, sig, w1T, g1, b1, m1, v1, bufA);
    conv_v3<64,128,32,16,8,false><<<B_TOTAL, 1024, smem2>>>(
        bufA, nullptr, w2T, g2, b2, m2, v2, bufB);
    conv_v3<128,256,16,8,4,false><<<B_TOTAL, 1024, smem3>>>(
        bufB, nullptr, w3T, g3, b3, m3, v3, bufA);
    conv4_kernel_v2<<<B_TOTAL / 4, 256>>>(bufA, w4, (float*)d_out);
}

// round 4
// speedup vs baseline: 1.0004x; 1.0004x over previous
#include <cuda_runtime.h>
#include <cstdint>

#define WV 14
#define WP 16          // padded width in global buffers (cols 0,15 zero)
#define P  20          // smem row pitch (floats), multiple of 4
#define B_TOTAL 2048

__device__ float g_bufA[(size_t)B_TOTAL * 32768];
__device__ float g_bufB[(size_t)B_TOTAL * 32768];
// Transposed weights [ci*9+k][co]: w1T @0, w2T @4096, w3T @81920
__device__ float g_wT[4096 + 73728 + 294912 + 1024];

typedef unsigned long long ull;

__device__ __forceinline__ ull pack2(float x) {
    ull r;
    asm("mov.b64 %0, {%1, %1};" : "=l"(r) : "f"(x));
    return r;
}
__device__ __forceinline__ void fma2(ull &acc, ull a, ull b) {
    asm("fma.rn.f32x2 %0, %1, %2, %0;" : "+l"(acc) : "l"(a), "l"(b));
}
__device__ __forceinline__ float2 unpack2(ull v) {
    float2 r;
    asm("mov.b64 {%0, %1}, %2;" : "=f"(r.x), "=f"(r.y) : "l"(v));
    return r;
}

// Weight transpose: w[co][ci][3][3] -> wT[ci*9+k][co]
__global__ void transpose_w_kernel(const float* __restrict__ w,
                                   float* __restrict__ wT,
                                   int CIN, int COUT)
{
    int i = blockIdx.x * 256 + threadIdx.x;
    int total = COUT * CIN * 9;
    if (i >= total) return;
    int co = i / (CIN * 9);
    int r  = i % (CIN * 9);
    wT[r * COUT + co] = w[i];
}

// =====================================================================
// Fused conv(3x3, stride (2,1), pad (1,1)) + BN + ReLU.  1024 threads.
// One CTA per sample. Whole input slab in smem, rows shifted +1 with
// row 0 = zeros (pad).  Thread = (wh, h, cp): 4 output channels
// co0=4cp, 7 width outputs (w_global = 7*wh + w).
// Requires 2 * HOUT * (COUT/4) == 1024.
// =====================================================================
template<int CIN, int COUT, int HIN, int HOUT, int CI_BLK, bool FIRST>
__global__ void __launch_bounds__(1024, 1)
conv_v3(const float* __restrict__ in0,
        const float* __restrict__ in1,    // sigmas when FIRST
        const float* __restrict__ wT,     // [CIN*9][COUT]
        const float* __restrict__ gam,
        const float* __restrict__ bet,
        const float* __restrict__ mu,
        const float* __restrict__ var,
        float* __restrict__ out)          // [B][COUT][HOUT][WP]
{
    constexpr int ROWS    = HIN + 1;
    constexpr int IN_SM   = CIN * ROWS * P;
    constexpr int W_ELEMS = CI_BLK * 9 * COUT;
    constexpr int CP4     = COUT / 4;

    extern __shared__ float smem[];
    float* s_in = smem;                 // [CIN][ROWS][P]
    float* s_w  = smem + IN_SM;         // [CI_BLK*9][COUT]

    const int b   = blockIdx.x;
    const int tid = threadIdx.x;

    // zero whole input slab (covers pad row/cols), then fill
    {
        float4 z = make_float4(0.f, 0.f, 0.f, 0.f);
        for (int i = tid * 4; i < IN_SM; i += 4096)
            *reinterpret_cast<float4*>(s_in + i) = z;
    }
    __syncthreads();

    if (FIRST) {
        // ch0 = x, ch1 = 10*sigmas; data cols 1..14, rows 1..HIN
        for (int i = tid; i < HIN * WV; i += 1024) {
            int f = i / WV, k = i % WV;
            s_in[(f + 1) * P + k + 1]              = in0[(size_t)b * (HIN * WV) + i];
            s_in[(ROWS + f + 1) * P + k + 1]       = in1[(size_t)b * (HIN * WV) + i] * 10.0f;
        }
    } else {
        const float* gin = in0 + (size_t)b * (CIN * HIN * WP);
        for (int e = tid; e < CIN * HIN * 4; e += 1024) {
            int i  = e * 4;
            int ci = i / (HIN * WP);
            int rm = i % (HIN * WP);
            int r  = rm >> 4;
            int c  = rm & 15;
            *reinterpret_cast<float4*>(s_in + ci * (ROWS * P) + (r + 1) * P + c) =
                *reinterpret_cast<const float4*>(gin + i);
        }
    }

    const int wh  = tid >> 9;           // warp-uniform
    const int rem = tid & 511;
    const int h   = rem / CP4;          // warp-uniform (CP4 >= 16)
    const int cp  = rem % CP4;
    const int co0 = cp * 4;

    ull accA[7], accB[7];
    #pragma unroll
    for (int w = 0; w < 7; w++) { accA[w] = 0ull; accB[w] = 0ull; }

    for (int ci0 = 0; ci0 < CIN; ci0 += CI_BLK) {
        __syncthreads();
        {   // coalesced weight staging from pre-transposed layout
            const float4* src =
                reinterpret_cast<const float4*>(wT + (size_t)ci0 * 9 * COUT);
            float4* dst = reinterpret_cast<float4*>(s_w);
            for (int e = tid; e < W_ELEMS / 4; e += 1024) dst[e] = src[e];
        }
        __syncthreads();

        for (int ci = 0; ci < CI_BLK; ci++) {
            const float* ib = s_in + (ci0 + ci) * (ROWS * P) + 4 * wh;
            const float* wb = s_w + ci * 9 * COUT + co0;
            #pragma unroll
            for (int kh = 0; kh < 3; kh++) {
                const float4* row4 =
                    reinterpret_cast<const float4*>(ib + (2 * h + kh) * P);
                float4 q0 = row4[0], q1 = row4[1], q2 = row4[2];
                ull pv[9];
                if (wh == 0) {
                    pv[0] = pack2(q0.x); pv[1] = pack2(q0.y); pv[2] = pack2(q0.z);
                    pv[3] = pack2(q0.w); pv[4] = pack2(q1.x); pv[5] = pack2(q1.y);
                    pv[6] = pack2(q1.z); pv[7] = pack2(q1.w); pv[8] = pack2(q2.x);
                } else {
                    pv[0] = pack2(q0.w); pv[1] = pack2(q1.x); pv[2] = pack2(q1.y);
                    pv[3] = pack2(q1.z); pv[4] = pack2(q1.w); pv[5] = pack2(q2.x);
                    pv[6] = pack2(q2.y); pv[7] = pack2(q2.z); pv[8] = pack2(q2.w);
                }
                #pragma unroll
                for (int kw = 0; kw < 3; kw++) {
                    ulonglong2 wp = *reinterpret_cast<const ulonglong2*>(
                        wb + (kh * 3 + kw) * COUT);
                    #pragma unroll
                    for (int w = 0; w < 7; w++) {
                        fma2(accA[w], pv[kw + w], wp.x);
                        fma2(accB[w], pv[kw + w], wp.y);
                    }
                }
            }
        }
    }

    // BN(eval) + ReLU epilogue: 4 channels x 7 width outputs
    float4 g4 = *reinterpret_cast<const float4*>(gam + co0);
    float4 b4 = *reinterpret_cast<const float4*>(bet + co0);
    float4 m4 = *reinterpret_cast<const float4*>(mu  + co0);
    float4 v4 = *reinterpret_cast<const float4*>(var + co0);
    float sc0 = g4.x * rsqrtf(v4.x + 1e-5f), sh0 = b4.x - m4.x * sc0;
    float sc1 = g4.y * rsqrtf(v4.y + 1e-5f), sh1 = b4.y - m4.y * sc1;
    float sc2 = g4.z * rsqrtf(v4.z + 1e-5f), sh2 = b4.z - m4.z * sc2;
    float sc3 = g4.w * rsqrtf(v4.w + 1e-5f), sh3 = b4.w - m4.w * sc3;

    float* r0 = out + (size_t)b * (COUT * HOUT * WP)
                    + (size_t)co0 * (HOUT * WP) + h * WP;
    float* r1 = r0 + HOUT * WP;
    float* r2 = r1 + HOUT * WP;
    float* r3 = r2 + HOUT * WP;
    int pc = wh ? (WV + 1) : 0;     // pad column this thread owns
    r0[pc] = 0.f; r1[pc] = 0.f; r2[pc] = 0.f; r3[pc] = 0.f;
    const int cbase = 1 + 7 * wh;
    #pragma unroll
    for (int w = 0; w < 7; w++) {
        float2 a = unpack2(accA[w]);
        float2 c = unpack2(accB[w]);
        r0[cbase + w] = fmaxf(fmaf(a.x, sc0, sh0), 0.f);
        r1[cbase + w] = fmaxf(fmaf(a.y, sc1, sh1), 0.f);
        r2[cbase + w] = fmaxf(fmaf(c.x, sc2, sh2), 0.f);
        r3[cbase + w] = fmaxf(fmaf(c.y, sc3, sh3), 0.f);
    }
}

// =====================================================================
// conv4: temporal merge (8,1), fused transpose. 2 warps/sample.
// =====================================================================
__global__ void __launch_bounds__(256)
conv4_kernel_v2(const float* __restrict__ in,   // [B][256][8][WP]
                const float* __restrict__ w4,   // [2][256][8][1]
                float* __restrict__ out)        // [B][14][2]
{
    __shared__ float part[8][28];
    const int warp = threadIdx.x >> 5;
    const int lane = threadIdx.x & 31;
    const int b    = blockIdx.x * 4 + (warp >> 1);
    const int half = warp & 1;

    const float* base = in + (size_t)b * 32768;
    float acc0[WV], acc1[WV];
    #pragma unroll
    for (int w = 0; w < WV; w++) { acc0[w] = 0.f; acc1[w] = 0.f; }

    const int ci_lo = 128 * half;
    for (int ci = ci_lo + lane; ci < ci_lo + 128; ci += 32) {
        const float* prow  = base + ci * (8 * WP);
        const float* wrow0 = w4 + ci * 8;
        const float* wrow1 = w4 + 2048 + ci * 8;
        #pragma unroll
        for (int kh = 0; kh < 8; kh++) {
            float w0 = wrow0[kh], w1 = wrow1[kh];
            const float4* r4 = reinterpret_cast<const float4*>(prow + kh * WP);
            float4 q0 = r4[0], q1 = r4[1], q2 = r4[2], q3 = r4[3];
            float v[16] = {q0.x,q0.y,q0.z,q0.w, q1.x,q1.y,q1.z,q1.w,
                           q2.x,q2.y,q2.z,q2.w, q3.x,q3.y,q3.z,q3.w};
            #pragma unroll
            for (int w = 0; w < WV; w++) {
                acc0[w] = fmaf(v[w + 1], w0, acc0[w]);
                acc1[w] = fmaf(v[w + 1], w1, acc1[w]);
            }
        }
    }
    #pragma unroll
    for (int off = 16; off > 0; off >>= 1) {
        #pragma unroll
        for (int w = 0; w < WV; w++) {
            acc0[w] += __shfl_down_sync(0xffffffffu, acc0[w], off);
            acc1[w] += __shfl_down_sync(0xffffffffu, acc1[w], off);
        }
    }
    if (lane == 0) {
        #pragma unroll
        for (int w = 0; w < WV; w++) {
            part[warp][w]      = acc0[w];
            part[warp][14 + w] = acc1[w];
        }
    }
    __syncthreads();
    if (threadIdx.x < 112) {
        int s = threadIdx.x / 28, j = threadIdx.x % 28;
        float v = part[2 * s][j] + part[2 * s + 1][j];
        int bb = blockIdx.x * 4 + s;
        int c = j / 14, w = j % 14;
        out[(size_t)bb * 28 + w * 2 + c] = v;
    }
}

extern "C" void kernel_launch(void* const* d_in, const int* in_sizes, int n_in,
                              void* d_out, int out_size)
{
    (void)n_in; (void)out_size;
    const float* x   = (const float*)d_in[0];
    const float* sig = (const float*)d_in[1];
    const float* w1  = (const float*)d_in[2];
    const float *w2, *w3, *w4;
    const float *g1,*b1,*m1,*v1,*g2,*b2,*m2,*v2,*g3,*b3,*m3,*v3;

    if (in_sizes[3] == 73728) {
        w2=(const float*)d_in[3];  w3=(const float*)d_in[4];  w4=(const float*)d_in[5];
        g1=(const float*)d_in[6];  b1=(const float*)d_in[7];  m1=(const float*)d_in[8];  v1=(const float*)d_in[9];
        g2=(const float*)d_in[10]; b2=(const float*)d_in[11]; m2=(const float*)d_in[12]; v2=(const float*)d_in[13];
        g3=(const float*)d_in[14]; b3=(const float*)d_in[15]; m3=(const float*)d_in[16]; v3=(const float*)d_in[17];
    } else {
        g1=(const float*)d_in[3];  b1=(const float*)d_in[4];  m1=(const float*)d_in[5];  v1=(const float*)d_in[6];
        w2=(const float*)d_in[7];
        g2=(const float*)d_in[8];  b2=(const float*)d_in[9];  m2=(const float*)d_in[10]; v2=(const float*)d_in[11];
        w3=(const float*)d_in[12];
        g3=(const float*)d_in[13]; b3=(const float*)d_in[14]; m3=(const float*)d_in[15]; v3=(const float*)d_in[16];
        w4=(const float*)d_in[17];
    }

    float *bufA = nullptr, *bufB = nullptr, *wT = nullptr;
    cudaGetSymbolAddress((void**)&bufA, g_bufA);
    cudaGetSymbolAddress((void**)&bufB, g_bufB);
    cudaGetSymbolAddress((void**)&wT,   g_wT);
    float* w1T = wT;
    float* w2T = wT + 4096;
    float* w3T = wT + 81920;

    transpose_w_kernel<<<(64 * 2 * 9 + 255) / 256, 256>>>(w1, w1T, 2, 64);
    transpose_w_kernel<<<(128 * 64 * 9 + 255) / 256, 256>>>(w2, w2T, 64, 128);
    transpose_w_kernel<<<(256 * 128 * 9 + 255) / 256, 256>>>(w3, w3T, 128, 256);

    const int smem1 = (2   * 65 * P + 2 * 9 * 64)  * 4;   //  15008 B
    const int smem2 = (64  * 33 * P + 8 * 9 * 128) * 4;   // 205824 B
    const int smem3 = (128 * 17 * P + 4 * 9 * 256) * 4;   // 210944 B

    cudaFuncSetAttribute(conv_v3<64,128,32,16,8,false>,
                         cudaFuncAttributeMaxDynamicSharedMemorySize, smem2);
    cudaFuncSetAttribute(conv_v3<128,256,16,8,4,false>,
                         cudaFuncAttributeMaxDynamicSharedMemorySize, smem3);

    conv_v3<2,64,64,32,2,true><<<B_TOTAL, 1024, smem1>>>(
        x, sig, w1T, g1, b1, m1, v1, bufA);
    conv_v3<64,128,32,16,8,false><<<B_TOTAL, 1024, smem2>>>(
        bufA, nullptr, w2T, g2, b2, m2, v2, bufB);
    conv_v3<128,256,16,8,4,false><<<B_TOTAL, 1024, smem3>>>(
        bufB, nullptr, w3T, g3, b3, m3, v3, bufA);
    conv4_kernel_v2<<<B_TOTAL / 4, 256>>>(bufA, w4, (float*)d_out);
}

// round 7
// speedup vs baseline: 2.8995x; 2.8984x over previous
#include <cuda_runtime.h>
#include <cuda_bf16.h>
#include <cstdint>

typedef unsigned long long ull;
typedef __nv_bfloat16 bf16;

#define B_N 2048

// ---------------- device scratch (zero-init at load; pad cells never written) ----
__device__ float g_in0F[2 * 65 * 16 * 2048];                 // conv1 input, padded CHWN
__device__ bf16  g_a1hi[(size_t)64 * 34 * 16 * 2048];        // conv1 out hi
__device__ bf16  g_a1lo[(size_t)64 * 34 * 16 * 2048];        // conv1 out lo
__device__ bf16  g_a2hi[(size_t)128 * 18 * 16 * 2048];       // conv2 out hi
__device__ bf16  g_a2lo[(size_t)128 * 18 * 16 * 2048];       // conv2 out lo
__device__ bf16  g_w2hi[128 * 576],  g_w2lo[128 * 576];
__device__ bf16  g_w3hi[256 * 1152], g_w3lo[256 * 1152];

// ---------------- helpers ----------------
__device__ __forceinline__ uint32_t smem_u32(const void* p) {
    uint32_t a;
    asm("{ .reg .u64 t; cvta.to.shared.u64 t, %1; cvt.u32.u64 %0, t; }"
        : "=r"(a) : "l"(p));
    return a;
}
__device__ __forceinline__ ull pack2(float x) {
    ull r; asm("mov.b64 %0, {%1, %1};" : "=l"(r) : "f"(x)); return r;
}
__device__ __forceinline__ void fma2(ull &acc, ull a, ull b) {
    asm("fma.rn.f32x2 %0, %1, %2, %0;" : "+l"(acc) : "l"(a), "l"(b));
}
__device__ __forceinline__ float2 unpack2(ull v) {
    float2 r; asm("mov.b64 {%0, %1}, %2;" : "=f"(r.x), "=f"(r.y) : "l"(v)); return r;
}
// pack two floats to bf16x2 (y0 -> low 16, y1 -> high 16)
__device__ __forceinline__ uint32_t cvt_bf16x2(float y0, float y1) {
    uint32_t r;
    asm("cvt.rn.bf16x2.f32 %0, %1, %2;" : "=r"(r) : "f"(y1), "f"(y0));
    return r;
}

// ldmatrix / mma.sync (base ISA, compiles for plain sm_103)
__device__ __forceinline__ void ldsm4(uint32_t* r, uint32_t a) {
    asm volatile("ldmatrix.sync.aligned.m8n8.x4.shared.b16 {%0,%1,%2,%3}, [%4];"
        : "=r"(r[0]), "=r"(r[1]), "=r"(r[2]), "=r"(r[3]) : "r"(a));
}
__device__ __forceinline__ void ldsm2t(uint32_t* r, uint32_t a) {
    asm volatile("ldmatrix.sync.aligned.m8n8.x2.trans.shared.b16 {%0,%1}, [%2];"
        : "=r"(r[0]), "=r"(r[1]) : "r"(a));
}
__device__ __forceinline__ void mma16816(float* d, const uint32_t* a, const uint32_t* b) {
    asm volatile(
        "mma.sync.aligned.m16n8k16.row.col.f32.bf16.bf16.f32 "
        "{%0,%1,%2,%3}, {%4,%5,%6,%7}, {%8,%9}, {%0,%1,%2,%3};"
        : "+f"(d[0]), "+f"(d[1]), "+f"(d[2]), "+f"(d[3])
        : "r"(a[0]), "r"(a[1]), "r"(a[2]), "r"(a[3]), "r"(b[0]), "r"(b[1]));
}

// ======================= small prep kernels =======================
__global__ void zero_out_kernel(float* p, int n) {
    int i = blockIdx.x * 1024 + threadIdx.x;
    if (i < n) p[i] = 0.f;
}

// x,sigmas [B][64][14] -> g_in0F [2][65][16][B] (pads stay zero)
__global__ void prep_input_kernel(const float* __restrict__ x,
                                  const float* __restrict__ sig) {
    int fk = blockIdx.x;            // 0..895
    int f = fk / 14, k = fk % 14;
    int t = threadIdx.x;
    for (int it = 0; it < 8; it++) {
        int b = it * 256 + t;
        float xv = x[(size_t)b * 896 + fk];
        float sv = sig[(size_t)b * 896 + fk] * 10.0f;
        g_in0F[((size_t)(0 * 65 + f + 1) * 16 + k + 1) * B_N + b] = xv;
        g_in0F[((size_t)(1 * 65 + f + 1) * 16 + k + 1) * B_N + b] = sv;
    }
}

__global__ void split_w_kernel(const float* __restrict__ w, bf16* __restrict__ hi,
                               bf16* __restrict__ lo, int n) {
    int i = blockIdx.x * 256 + threadIdx.x;
    if (i >= n) return;
    float f = w[i];
    bf16 h = __float2bfloat16_rn(f);
    hi[i] = h;
    lo[i] = __float2bfloat16_rn(f - __bfloat162float(h));
}

// ======================= conv1 (scalar fp32 -> bf16 split CHWN) ===========
__global__ void __launch_bounds__(256, 2)
conv1_kernel(const float* __restrict__ w1,   // [64][2][3][3]
             const float* __restrict__ g1, const float* __restrict__ b1,
             const float* __restrict__ m1, const float* __restrict__ v1)
{
    __shared__ float sw[1152];
    const int w = blockIdx.x, h = blockIdx.y;
    const int t = threadIdx.x;
    for (int i = t; i < 1152; i += 256) sw[i] = w1[i];
    __syncthreads();

    const int b0 = (blockIdx.z * 256 + t) * 4;
    ull u[18][2];
    #pragma unroll
    for (int ci = 0; ci < 2; ci++)
        #pragma unroll
        for (int kh = 0; kh < 3; kh++)
            #pragma unroll
            for (int kw = 0; kw < 3; kw++) {
                int idx = ci * 9 + kh * 3 + kw;
                const ull* p = reinterpret_cast<const ull*>(
                    g_in0F + ((size_t)(ci * 65 + 2 * h + kh) * 16 + w + kw) * B_N + b0);
                u[idx][0] = p[0];
                u[idx][1] = p[1];
            }

    for (int co = 0; co < 64; co++) {
        ull a0 = 0ull, a1 = 0ull;
        #pragma unroll
        for (int idx = 0; idx < 18; idx++) {
            ull wv = pack2(sw[co * 18 + idx]);
            fma2(a0, u[idx][0], wv);
            fma2(a1, u[idx][1], wv);
        }
        float sc = __ldg(g1 + co) * rsqrtf(__ldg(v1 + co) + 1e-5f);
        float sh = __ldg(b1 + co) - __ldg(m1 + co) * sc;
        float2 p0 = unpack2(a0), p1 = unpack2(a1);
        float y0 = fmaxf(fmaf(p0.x, sc, sh), 0.f);
        float y1 = fmaxf(fmaf(p0.y, sc, sh), 0.f);
        float y2 = fmaxf(fmaf(p1.x, sc, sh), 0.f);
        float y3 = fmaxf(fmaf(p1.y, sc, sh), 0.f);
        uint32_t h01 = cvt_bf16x2(y0, y1), h23 = cvt_bf16x2(y2, y3);
        float l0 = y0 - __uint_as_float(h01 << 16);
        float l1 = y1 - __uint_as_float(h01 & 0xFFFF0000u);
        float l2 = y2 - __uint_as_float(h23 << 16);
        float l3 = y3 - __uint_as_float(h23 & 0xFFFF0000u);
        uint32_t lo01 = cvt_bf16x2(l0, l1), lo23 = cvt_bf16x2(l2, l3);
        size_t addr = ((size_t)(co * 34 + h + 1) * 16 + w + 1) * B_N + b0;
        *reinterpret_cast<uint32_t*>(g_a1hi + addr)     = h01;
        *reinterpret_cast<uint32_t*>(g_a1hi + addr + 2) = h23;
        *reinterpret_cast<uint32_t*>(g_a1lo + addr)     = lo01;
        *reinterpret_cast<uint32_t*>(g_a1lo + addr + 2) = lo23;
    }
}

// ======================= mma.sync conv GEMM =======================
// CTA: D[128 co][128 n], K = CHUNKS*64.  8 warps (4 m x 2 n), warp 32co x 64n.
// bf16 hi/lo 3-pass:  D = Ahi*Bhi + Ahi*Blo + Alo*Bhi.
// SMEM: A [128co][64k] pitch 72 bf16 (144B), B [64k][128n] pitch 136 bf16 (272B).
static constexpr int OFF_AHI = 0;            // 128*144 = 18432
static constexpr int OFF_ALO = 18432;
static constexpr int OFF_BHI = 36864;        // 64*272 = 17408
static constexpr int OFF_BLO = 54272;
static constexpr int OFF_PART = 71680;       // 256 floats
static constexpr int SMEM_TOT = 72704;

template<int HPIN, int CHUNKS, bool FUSE4>
__global__ void __launch_bounds__(256, 2)
conv_mma(const bf16* __restrict__ Xhi, const bf16* __restrict__ Xlo,
         const bf16* __restrict__ Whi, const bf16* __restrict__ Wlo,
         const float* __restrict__ gam, const float* __restrict__ bet,
         const float* __restrict__ mu,  const float* __restrict__ var,
         const float* __restrict__ w4,
         bf16* __restrict__ Ohi, bf16* __restrict__ Olo,
         float* __restrict__ dout, int HP_OUT)
{
    constexpr int KTOT = CHUNKS * 64;
    extern __shared__ __align__(16) char smem[];
    const uint32_t smb = smem_u32(smem);
    float* s_part = reinterpret_cast<float*>(smem + OFF_PART);

    const int tid  = threadIdx.x;
    const int lane = tid & 31, wid = tid >> 5;
    const int wm = wid & 3, wn = wid >> 2;          // warp grid 4m x 2n
    const int g = lane >> 2, t = lane & 3;
    const int n0 = blockIdx.x * 128;
    const int h  = blockIdx.y;
    const int mtile = blockIdx.z;
    const int w_pos = n0 >> 11;                     // 2048 n per w => one w per CTA
    const int b0    = n0 & 2047;

    if (FUSE4) for (int i = tid; i < 256; i += 256) s_part[i] = 0.f;

    // ldmatrix lane addresses
    const int rA = lane & 15;
    const int kA = (lane >> 4) << 3;
    uint32_t aHi0 = smb + OFF_AHI + (uint32_t)((wm * 32 +  0 + rA) * 144 + kA * 2);
    uint32_t aHi1 = smb + OFF_AHI + (uint32_t)((wm * 32 + 16 + rA) * 144 + kA * 2);
    uint32_t aLo0 = aHi0 + (OFF_ALO - OFF_AHI);
    uint32_t aLo1 = aHi1 + (OFF_ALO - OFF_AHI);
    uint32_t bHiA = smb + OFF_BHI + (uint32_t)((lane & 15) * 272 + wn * 64 * 2);
    uint32_t bLoA = bHiA + (OFF_BLO - OFF_BHI);

    float acc[2][8][4];
    #pragma unroll
    for (int mt = 0; mt < 2; mt++)
        #pragma unroll
        for (int nt = 0; nt < 8; nt++)
            #pragma unroll
            for (int i = 0; i < 4; i++) acc[mt][nt][i] = 0.f;

    #pragma unroll 1
    for (int c = 0; c < CHUNKS; c++) {
        __syncthreads();
        // ---- stage A (weights [128co][64k], hi+lo) ----
        for (int v = tid; v < 1024; v += 256) {
            int row = v >> 3, k8 = v & 7;
            size_t go = (size_t)(mtile * 128 + row) * KTOT + c * 64 + k8 * 8;
            uint32_t so = (uint32_t)(row * 144 + k8 * 16);
            *reinterpret_cast<uint4*>(smem + OFF_AHI + so) =
                *reinterpret_cast<const uint4*>(Whi + go);
            *reinterpret_cast<uint4*>(smem + OFF_ALO + so) =
                *reinterpret_cast<const uint4*>(Wlo + go);
        }
        // ---- stage B (acts [64k][128n], direct copy, hi+lo) ----
        for (int v = tid; v < 1024; v += 256) {
            int row = v >> 4, n8 = v & 15;
            int k = c * 64 + row;
            int ci = k / 9;
            int r9 = k - ci * 9;
            int kh = r9 / 3;
            int kw = r9 - kh * 3;
            size_t go = ((size_t)(ci * HPIN + 2 * h + kh) * 16 + w_pos + kw) * B_N
                        + b0 + n8 * 8;
            uint32_t so = (uint32_t)(row * 272 + n8 * 16);
            *reinterpret_cast<uint4*>(smem + OFF_BHI + so) =
                *reinterpret_cast<const uint4*>(Xhi + go);
            *reinterpret_cast<uint4*>(smem + OFF_BLO + so) =
                *reinterpret_cast<const uint4*>(Xlo + go);
        }
        __syncthreads();

        #pragma unroll
        for (int ks = 0; ks < 4; ks++) {
            uint32_t Ah0[4], Ah1[4], Al0[4], Al1[4];
            ldsm4(Ah0, aHi0 + ks * 32);
            ldsm4(Ah1, aHi1 + ks * 32);
            ldsm4(Al0, aLo0 + ks * 32);
            ldsm4(Al1, aLo1 + ks * 32);
            #pragma unroll
            for (int nt = 0; nt < 8; nt++) {
                uint32_t bh[2], bl[2];
                ldsm2t(bh, bHiA + ks * (16 * 272) + nt * 16);
                ldsm2t(bl, bLoA + ks * (16 * 272) + nt * 16);
                mma16816(acc[0][nt], Ah0, bh);
                mma16816(acc[0][nt], Ah0, bl);
                mma16816(acc[0][nt], Al0, bh);
                mma16816(acc[1][nt], Ah1, bh);
                mma16816(acc[1][nt], Ah1, bl);
                mma16816(acc[1][nt], Al1, bh);
            }
        }
    }

    // ======================= epilogue =======================
    const int co_base = mtile * 128 + wm * 32;
    if (!FUSE4) {
        #pragma unroll
        for (int mt = 0; mt < 2; mt++) {
            int co0 = co_base + mt * 16 + g, co1 = co0 + 8;
            float sc0 = gam[co0] * rsqrtf(var[co0] + 1e-5f);
            float sh0 = bet[co0] - mu[co0] * sc0;
            float sc1 = gam[co1] * rsqrtf(var[co1] + 1e-5f);
            float sh1 = bet[co1] - mu[co1] * sc1;
            size_t base0 = ((size_t)(co0 * HP_OUT + h + 1) * 16 + w_pos + 1) * B_N + b0;
            size_t base1 = ((size_t)(co1 * HP_OUT + h + 1) * 16 + w_pos + 1) * B_N + b0;
            #pragma unroll
            for (int nt = 0; nt < 8; nt++) {
                int nl = wn * 64 + nt * 8 + 2 * t;
                float y0 = fmaxf(fmaf(acc[mt][nt][0], sc0, sh0), 0.f);
                float y1 = fmaxf(fmaf(acc[mt][nt][1], sc0, sh0), 0.f);
                float y2 = fmaxf(fmaf(acc[mt][nt][2], sc1, sh1), 0.f);
                float y3 = fmaxf(fmaf(acc[mt][nt][3], sc1, sh1), 0.f);
                uint32_t h01 = cvt_bf16x2(y0, y1);
                float l0 = y0 - __uint_as_float(h01 << 16);
                float l1 = y1 - __uint_as_float(h01 & 0xFFFF0000u);
                uint32_t lo01 = cvt_bf16x2(l0, l1);
                uint32_t h23 = cvt_bf16x2(y2, y3);
                float l2 = y2 - __uint_as_float(h23 << 16);
                float l3 = y3 - __uint_as_float(h23 & 0xFFFF0000u);
                uint32_t lo23 = cvt_bf16x2(l2, l3);
                *reinterpret_cast<uint32_t*>(Ohi + base0 + nl) = h01;
                *reinterpret_cast<uint32_t*>(Olo + base0 + nl) = lo01;
                *reinterpret_cast<uint32_t*>(Ohi + base1 + nl) = h23;
                *reinterpret_cast<uint32_t*>(Olo + base1 + nl) = lo23;
            }
        }
    } else {
        float p0[16], p1[16];
        #pragma unroll
        for (int j = 0; j < 16; j++) { p0[j] = 0.f; p1[j] = 0.f; }
        #pragma unroll
        for (int mt = 0; mt < 2; mt++) {
            int co0 = co_base + mt * 16 + g, co1 = co0 + 8;
            float sc0 = gam[co0] * rsqrtf(var[co0] + 1e-5f);
            float sh0 = bet[co0] - mu[co0] * sc0;
            float sc1 = gam[co1] * rsqrtf(var[co1] + 1e-5f);
            float sh1 = bet[co1] - mu[co1] * sc1;
            float wa0 = w4[co0 * 8 + h], wb0 = w4[2048 + co0 * 8 + h];
            float wa1 = w4[co1 * 8 + h], wb1 = w4[2048 + co1 * 8 + h];
            #pragma unroll
            for (int nt = 0; nt < 8; nt++) {
                float y0 = fmaxf(fmaf(acc[mt][nt][0], sc0, sh0), 0.f);
                float y1 = fmaxf(fmaf(acc[mt][nt][1], sc0, sh0), 0.f);
                float y2 = fmaxf(fmaf(acc[mt][nt][2], sc1, sh1), 0.f);
                float y3 = fmaxf(fmaf(acc[mt][nt][3], sc1, sh1), 0.f);
                p0[nt * 2]     += y0 * wa0 + y2 * wa1;
                p0[nt * 2 + 1] += y1 * wa0 + y3 * wa1;
                p1[nt * 2]     += y0 * wb0 + y2 * wb1;
                p1[nt * 2 + 1] += y1 * wb0 + y3 * wb1;
            }
        }
        // reduce over g (8 lanes, stride 4)
        #pragma unroll
        for (int off = 4; off <= 16; off <<= 1) {
            #pragma unroll
            for (int j = 0; j < 16; j++) {
                p0[j] += __shfl_xor_sync(0xffffffffu, p0[j], off);
                p1[j] += __shfl_xor_sync(0xffffffffu, p1[j], off);
            }
        }
        if (g == 0) {
            #pragma unroll
            for (int j = 0; j < 16; j++) {
                int nl = wn * 64 + (j >> 1) * 8 + 2 * t + (j & 1);
                atomicAdd(&s_part[nl * 2],     p0[j]);
                atomicAdd(&s_part[nl * 2 + 1], p1[j]);
            }
        }
        __syncthreads();
        for (int i = tid; i < 256; i += 256) {
            int nl = i >> 1, ch = i & 1;
            atomicAdd(dout + (size_t)(b0 + nl) * 28 + w_pos * 2 + ch, s_part[i]);
        }
    }
}

// ======================= host launch =======================
extern "C" void kernel_launch(void* const* d_in, const int* in_sizes, int n_in,
                              void* d_out, int out_size)
{
    (void)n_in;
    const float* x   = (const float*)d_in[0];
    const float* sig = (const float*)d_in[1];
    const float* w1  = (const float*)d_in[2];
    const float *w2, *w3, *w4;
    const float *g1,*b1,*m1,*v1,*g2,*b2,*m2,*v2,*g3,*b3,*m3,*v3;

    if (in_sizes[3] == 73728) {
        w2=(const float*)d_in[3];  w3=(const float*)d_in[4];  w4=(const float*)d_in[5];
        g1=(const float*)d_in[6];  b1=(const float*)d_in[7];  m1=(const float*)d_in[8];  v1=(const float*)d_in[9];
        g2=(const float*)d_in[10]; b2=(const float*)d_in[11]; m2=(const float*)d_in[12]; v2=(const float*)d_in[13];
        g3=(const float*)d_in[14]; b3=(const float*)d_in[15]; m3=(const float*)d_in[16]; v3=(const float*)d_in[17];
    } else {
        g1=(const float*)d_in[3];  b1=(const float*)d_in[4];  m1=(const float*)d_in[5];  v1=(const float*)d_in[6];
        w2=(const float*)d_in[7];
        g2=(const float*)d_in[8];  b2=(const float*)d_in[9];  m2=(const float*)d_in[10]; v2=(const float*)d_in[11];
        w3=(const float*)d_in[12];
        g3=(const float*)d_in[13]; b3=(const float*)d_in[14]; m3=(const float*)d_in[15]; v3=(const float*)d_in[16];
        w4=(const float*)d_in[17];
    }

    bf16 *a1hi, *a1lo, *a2hi, *a2lo, *w2hi, *w2lo, *w3hi, *w3lo;
    cudaGetSymbolAddress((void**)&a1hi, g_a1hi);
    cudaGetSymbolAddress((void**)&a1lo, g_a1lo);
    cudaGetSymbolAddress((void**)&a2hi, g_a2hi);
    cudaGetSymbolAddress((void**)&a2lo, g_a2lo);
    cudaGetSymbolAddress((void**)&w2hi, g_w2hi);
    cudaGetSymbolAddress((void**)&w2lo, g_w2lo);
    cudaGetSymbolAddress((void**)&w3hi, g_w3hi);
    cudaGetSymbolAddress((void**)&w3lo, g_w3lo);

    cudaFuncSetAttribute(conv_mma<34, 9, false>,
                         cudaFuncAttributeMaxDynamicSharedMemorySize, SMEM_TOT);
    cudaFuncSetAttribute(conv_mma<18, 18, true>,
                         cudaFuncAttributeMaxDynamicSharedMemorySize, SMEM_TOT);

    // 0) zero the output accumulator (conv4 accumulates via atomics)
    zero_out_kernel<<<(out_size + 1023) / 1024, 1024>>>((float*)d_out, out_size);
    // 1) input -> padded fp32 CHWN
    prep_input_kernel<<<896, 256>>>(x, sig);
    // 2) weight bf16 splits
    split_w_kernel<<<(73728 + 255) / 256, 256>>>(w2, w2hi, w2lo, 73728);
    split_w_kernel<<<(294912 + 255) / 256, 256>>>(w3, w3hi, w3lo, 294912);
    // 3) conv1 scalar -> a1 (bf16 split, padded CHWN)
    conv1_kernel<<<dim3(14, 32, 2), 256>>>(w1, g1, b1, m1, v1);
    // 4) conv2 tensor-core (mma.sync) -> a2
    conv_mma<34, 9, false><<<dim3(224, 16, 1), 256, SMEM_TOT>>>(
        a1hi, a1lo, w2hi, w2lo, g2, b2, m2, v2, nullptr,
        a2hi, a2lo, nullptr, 18);
    // 5) conv3 tensor-core + fused conv4 -> d_out
    conv_mma<18, 18, true><<<dim3(224, 8, 2), 256, SMEM_TOT>>>(
        a2hi, a2lo, w3hi, w3lo, g3, b3, m3, v3, w4,
        nullptr, nullptr, (float*)d_out, 0);
}

// round 8
// speedup vs baseline: 3.4849x; 1.2019x over previous
#include <cuda_runtime.h>
#include <cuda_bf16.h>
#include <cstdint>

typedef unsigned long long ull;
typedef __nv_bfloat16 bf16;

#define B_N 2048

// ---------------- device scratch (zero-init at load; pad cells never written) ----
__device__ float g_in0F[2 * 65 * 16 * 2048];                 // conv1 input, padded CHWN
__device__ bf16  g_a1hi[(size_t)64 * 34 * 16 * 2048];        // conv1 out hi
__device__ bf16  g_a1lo[(size_t)64 * 34 * 16 * 2048];        // conv1 out lo
__device__ bf16  g_a2hi[(size_t)128 * 18 * 16 * 2048];       // conv2 out hi
__device__ bf16  g_a2lo[(size_t)128 * 18 * 16 * 2048];       // conv2 out lo
__device__ bf16  g_w2hi[128 * 576],  g_w2lo[128 * 576];
__device__ bf16  g_w3hi[256 * 1152], g_w3lo[256 * 1152];

// ---------------- helpers ----------------
__device__ __forceinline__ uint32_t smem_u32(const void* p) {
    uint32_t a;
    asm("{ .reg .u64 t; cvta.to.shared.u64 t, %1; cvt.u32.u64 %0, t; }"
        : "=r"(a) : "l"(p));
    return a;
}
__device__ __forceinline__ ull pack2(float x) {
    ull r; asm("mov.b64 %0, {%1, %1};" : "=l"(r) : "f"(x)); return r;
}
__device__ __forceinline__ void fma2(ull &acc, ull a, ull b) {
    asm("fma.rn.f32x2 %0, %1, %2, %0;" : "+l"(acc) : "l"(a), "l"(b));
}
__device__ __forceinline__ float2 unpack2(ull v) {
    float2 r; asm("mov.b64 {%0, %1}, %2;" : "=f"(r.x), "=f"(r.y) : "l"(v)); return r;
}
__device__ __forceinline__ uint32_t cvt_bf16x2(float y0, float y1) {
    uint32_t r;
    asm("cvt.rn.bf16x2.f32 %0, %1, %2;" : "=r"(r) : "f"(y1), "f"(y0));
    return r;
}

// ldmatrix / mma.sync (base ISA)
__device__ __forceinline__ void ldsm4(uint32_t* r, uint32_t a) {
    asm volatile("ldmatrix.sync.aligned.m8n8.x4.shared.b16 {%0,%1,%2,%3}, [%4];"
        : "=r"(r[0]), "=r"(r[1]), "=r"(r[2]), "=r"(r[3]) : "r"(a));
}
__device__ __forceinline__ void ldsm2t(uint32_t* r, uint32_t a) {
    asm volatile("ldmatrix.sync.aligned.m8n8.x2.trans.shared.b16 {%0,%1}, [%2];"
        : "=r"(r[0]), "=r"(r[1]) : "r"(a));
}
__device__ __forceinline__ void mma16816(float* d, const uint32_t* a, const uint32_t* b) {
    asm volatile(
        "mma.sync.aligned.m16n8k16.row.col.f32.bf16.bf16.f32 "
        "{%0,%1,%2,%3}, {%4,%5,%6,%7}, {%8,%9}, {%0,%1,%2,%3};"
        : "+f"(d[0]), "+f"(d[1]), "+f"(d[2]), "+f"(d[3])
        : "r"(a[0]), "r"(a[1]), "r"(a[2]), "r"(a[3]), "r"(b[0]), "r"(b[1]));
}

// cp.async
#define CP_ASYNC16(dst, src) \
    asm volatile("cp.async.cg.shared.global [%0], [%1], 16;" :: "r"(dst), "l"(src))
#define CP_COMMIT() asm volatile("cp.async.commit_group;" ::: "memory")
#define CP_WAIT0()  asm volatile("cp.async.wait_group 0;" ::: "memory")
#define CP_WAIT1()  asm volatile("cp.async.wait_group 1;" ::: "memory")

// ======================= small prep kernels =======================
__global__ void zero_out_kernel(float* p, int n) {
    int i = blockIdx.x * 1024 + threadIdx.x;
    if (i < n) p[i] = 0.f;
}

// x,sigmas [B][64][14] -> g_in0F [2][65][16][B]
__global__ void prep_input_kernel(const float* __restrict__ x,
                                  const float* __restrict__ sig) {
    int fk = blockIdx.x;            // 0..895
    int f = fk / 14, k = fk % 14;
    int t = threadIdx.x;
    for (int it = 0; it < 8; it++) {
        int b = it * 256 + t;
        float xv = x[(size_t)b * 896 + fk];
        float sv = sig[(size_t)b * 896 + fk] * 10.0f;
        g_in0F[((size_t)(0 * 65 + f + 1) * 16 + k + 1) * B_N + b] = xv;
        g_in0F[((size_t)(1 * 65 + f + 1) * 16 + k + 1) * B_N + b] = sv;
    }
}

__global__ void split_w_kernel(const float* __restrict__ w, bf16* __restrict__ hi,
                               bf16* __restrict__ lo, int n) {
    int i = blockIdx.x * 256 + threadIdx.x;
    if (i >= n) return;
    float f = w[i];
    bf16 h = __float2bfloat16_rn(f);
    hi[i] = h;
    lo[i] = __float2bfloat16_rn(f - __bfloat162float(h));
}

// ======================= conv1 (scalar fp32 -> bf16 split CHWN) ===========
__global__ void __launch_bounds__(256, 2)
conv1_kernel(const float* __restrict__ w1,   // [64][2][3][3]
             const float* __restrict__ g1, const float* __restrict__ b1,
             const float* __restrict__ m1, const float* __restrict__ v1)
{
    __shared__ float sw[1152];
    const int w = blockIdx.x, h = blockIdx.y;
    const int t = threadIdx.x;
    for (int i = t; i < 1152; i += 256) sw[i] = w1[i];
    __syncthreads();

    const int b0 = (blockIdx.z * 256 + t) * 4;
    ull u[18][2];
    #pragma unroll
    for (int ci = 0; ci < 2; ci++)
        #pragma unroll
        for (int kh = 0; kh < 3; kh++)
            #pragma unroll
            for (int kw = 0; kw < 3; kw++) {
                int idx = ci * 9 + kh * 3 + kw;
                const ull* p = reinterpret_cast<const ull*>(
                    g_in0F + ((size_t)(ci * 65 + 2 * h + kh) * 16 + w + kw) * B_N + b0);
                u[idx][0] = p[0];
                u[idx][1] = p[1];
            }

    for (int co = 0; co < 64; co++) {
        ull a0 = 0ull, a1 = 0ull;
        #pragma unroll
        for (int idx = 0; idx < 18; idx++) {
            ull wv = pack2(sw[co * 18 + idx]);
            fma2(a0, u[idx][0], wv);
            fma2(a1, u[idx][1], wv);
        }
        float sc = __ldg(g1 + co) * rsqrtf(__ldg(v1 + co) + 1e-5f);
        float sh = __ldg(b1 + co) - __ldg(m1 + co) * sc;
        float2 p0 = unpack2(a0), p1 = unpack2(a1);
        float y0 = fmaxf(fmaf(p0.x, sc, sh), 0.f);
        float y1 = fmaxf(fmaf(p0.y, sc, sh), 0.f);
        float y2 = fmaxf(fmaf(p1.x, sc, sh), 0.f);
        float y3 = fmaxf(fmaf(p1.y, sc, sh), 0.f);
        uint32_t h01 = cvt_bf16x2(y0, y1), h23 = cvt_bf16x2(y2, y3);
        float l0 = y0 - __uint_as_float(h01 << 16);
        float l1 = y1 - __uint_as_float(h01 & 0xFFFF0000u);
        float l2 = y2 - __uint_as_float(h23 << 16);
        float l3 = y3 - __uint_as_float(h23 & 0xFFFF0000u);
        uint32_t lo01 = cvt_bf16x2(l0, l1), lo23 = cvt_bf16x2(l2, l3);
        size_t addr = ((size_t)(co * 34 + h + 1) * 16 + w + 1) * B_N + b0;
        *reinterpret_cast<uint32_t*>(g_a1hi + addr)     = h01;
        *reinterpret_cast<uint32_t*>(g_a1hi + addr + 2) = h23;
        *reinterpret_cast<uint32_t*>(g_a1lo + addr)     = lo01;
        *reinterpret_cast<uint32_t*>(g_a1lo + addr + 2) = lo23;
    }
}

// ======================= mma.sync conv GEMM v3 =======================
// CTA: D[128 co][256 n], K = CHUNKS*64, 512 threads (16 warps, 4m x 4n),
// warp = 32co x 64n.  bf16 hi/lo 3-pass.  cp.async double-buffered chunks.
// Per-buffer layout: A hi [128][72bf16] @0, A lo @18432,
//                    B hi [64][264bf16] @36864, B lo @70656.  BUF_SZ=104448.
static constexpr int OFF_ALO_L = 18432;
static constexpr int OFF_BHI_L = 36864;
static constexpr int OFF_BLO_L = 70656;
static constexpr int BUF_SZ    = 104448;
static constexpr int OFF_PART  = 2 * BUF_SZ;        // 512 floats (FUSE4)
static constexpr int SMEM_TOT  = OFF_PART + 2048;   // 210944

template<int HPIN, int CHUNKS, bool FUSE4>
__global__ void __launch_bounds__(512, 1)
conv_mma(const bf16* __restrict__ Xhi, const bf16* __restrict__ Xlo,
         const bf16* __restrict__ Whi, const bf16* __restrict__ Wlo,
         const float* __restrict__ gam, const float* __restrict__ bet,
         const float* __restrict__ mu,  const float* __restrict__ var,
         const float* __restrict__ w4,
         bf16* __restrict__ Ohi, bf16* __restrict__ Olo,
         float* __restrict__ dout, int HP_OUT)
{
    constexpr int KTOT = CHUNKS * 64;
    extern __shared__ __align__(16) char smem[];
    const uint32_t smb = smem_u32(smem);
    float* s_part = reinterpret_cast<float*>(smem + OFF_PART);

    const int tid  = threadIdx.x;
    const int lane = tid & 31, wid = tid >> 5;
    const int wm = wid & 3, wn = wid >> 2;          // 4m x 4n warps
    const int g = lane >> 2, t = lane & 3;
    const int n0 = blockIdx.x * 256;
    const int h  = blockIdx.y;
    const int mtile = blockIdx.z;
    const int w_pos = n0 >> 11;
    const int b0    = n0 & 2047;

    if (FUSE4 && tid < 512) s_part[tid] = 0.f;

    // ldmatrix lane addresses (offsets within a buffer)
    const int rA = lane & 15;
    const int kA = (lane >> 4) << 3;
    const uint32_t aOff0 = (uint32_t)((wm * 32 +  0 + rA) * 144 + kA * 2);
    const uint32_t aOff1 = (uint32_t)((wm * 32 + 16 + rA) * 144 + kA * 2);
    const uint32_t bOff  = (uint32_t)(OFF_BHI_L + (lane & 15) * 528 + wn * 128);

    float acc[2][8][4];
    #pragma unroll
    for (int mt = 0; mt < 2; mt++)
        #pragma unroll
        for (int nt = 0; nt < 8; nt++)
            #pragma unroll
            for (int i = 0; i < 4; i++) acc[mt][nt][i] = 0.f;

    // ---- async stage of chunk cc into buffer bufOff ----
    auto stage = [&](int cc, uint32_t bufOff) {
        // A: weights [128co][64k] hi+lo
        #pragma unroll
        for (int it = 0; it < 2; it++) {
            int e = it * 512 + tid;                 // 0..1023
            int row = e >> 3, k8 = e & 7;
            size_t go = (size_t)(mtile * 128 + row) * KTOT + cc * 64 + k8 * 8;
            uint32_t so = smb + bufOff + (uint32_t)(row * 144 + k8 * 16);
            CP_ASYNC16(so,             Whi + go);
            CP_ASYNC16(so + OFF_ALO_L, Wlo + go);
        }
        // B: acts [64k][256n] hi+lo
        #pragma unroll
        for (int it = 0; it < 4; it++) {
            int e = it * 512 + tid;                 // 0..2047
            int row = e >> 5, n16 = e & 31;
            int k = cc * 64 + row;
            int ci = k / 9;
            int r9 = k - ci * 9;
            int kh = r9 / 3;
            int kw = r9 - kh * 3;
            size_t go = ((size_t)(ci * HPIN + 2 * h + kh) * 16 + w_pos + kw) * B_N
                        + b0 + n16 * 8;
            uint32_t so = smb + bufOff + (uint32_t)(OFF_BHI_L + row * 528 + n16 * 16);
            CP_ASYNC16(so,                         Xhi + go);
            CP_ASYNC16(so + (OFF_BLO_L - OFF_BHI_L), Xlo + go);
        }
        CP_COMMIT();
    };

    stage(0, 0);

    #pragma unroll 1
    for (int c = 0; c < CHUNKS; c++) {
        const uint32_t cur = (c & 1) ? BUF_SZ : 0;
        if (c + 1 < CHUNKS) {
            stage(c + 1, cur ^ BUF_SZ);
            CP_WAIT1();
        } else {
            CP_WAIT0();
        }
        __syncthreads();

        const uint32_t aHi0 = smb + cur + aOff0;
        const uint32_t aHi1 = smb + cur + aOff1;
        const uint32_t bA   = smb + cur + bOff;
        #pragma unroll
        for (int ks = 0; ks < 4; ks++) {
            uint32_t Ah0[4], Ah1[4], Al0[4], Al1[4];
            ldsm4(Ah0, aHi0 + ks * 32);
            ldsm4(Ah1, aHi1 + ks * 32);
            ldsm4(Al0, aHi0 + OFF_ALO_L + ks * 32);
            ldsm4(Al1, aHi1 + OFF_ALO_L + ks * 32);
            #pragma unroll
            for (int nt = 0; nt < 8; nt++) {
                uint32_t bh[2], bl[2];
                ldsm2t(bh, bA + ks * 8448 + nt * 16);
                ldsm2t(bl, bA + (OFF_BLO_L - OFF_BHI_L) + ks * 8448 + nt * 16);
                mma16816(acc[0][nt], Ah0, bh);
                mma16816(acc[0][nt], Ah0, bl);
                mma16816(acc[0][nt], Al0, bh);
                mma16816(acc[1][nt], Ah1, bh);
                mma16816(acc[1][nt], Ah1, bl);
                mma16816(acc[1][nt], Al1, bh);
            }
        }
        __syncthreads();
    }

    // ======================= epilogue =======================
    const int co_base = mtile * 128 + wm * 32;
    if (!FUSE4) {
        #pragma unroll
        for (int mt = 0; mt < 2; mt++) {
            int co0 = co_base + mt * 16 + g, co1 = co0 + 8;
            float sc0 = gam[co0] * rsqrtf(var[co0] + 1e-5f);
            float sh0 = bet[co0] - mu[co0] * sc0;
            float sc1 = gam[co1] * rsqrtf(var[co1] + 1e-5f);
            float sh1 = bet[co1] - mu[co1] * sc1;
            size_t base0 = ((size_t)(co0 * HP_OUT + h + 1) * 16 + w_pos + 1) * B_N + b0;
            size_t base1 = ((size_t)(co1 * HP_OUT + h + 1) * 16 + w_pos + 1) * B_N + b0;
            #pragma unroll
            for (int nt = 0; nt < 8; nt++) {
                int nl = wn * 64 + nt * 8 + 2 * t;
                float y0 = fmaxf(fmaf(acc[mt][nt][0], sc0, sh0), 0.f);
                float y1 = fmaxf(fmaf(acc[mt][nt][1], sc0, sh0), 0.f);
                float y2 = fmaxf(fmaf(acc[mt][nt][2], sc1, sh1), 0.f);
                float y3 = fmaxf(fmaf(acc[mt][nt][3], sc1, sh1), 0.f);
                uint32_t h01 = cvt_bf16x2(y0, y1);
                float l0 = y0 - __uint_as_float(h01 << 16);
                float l1 = y1 - __uint_as_float(h01 & 0xFFFF0000u);
                uint32_t lo01 = cvt_bf16x2(l0, l1);
                uint32_t h23 = cvt_bf16x2(y2, y3);
                float l2 = y2 - __uint_as_float(h23 << 16);
                float l3 = y3 - __uint_as_float(h23 & 0xFFFF0000u);
                uint32_t lo23 = cvt_bf16x2(l2, l3);
                *reinterpret_cast<uint32_t*>(Ohi + base0 + nl) = h01;
                *reinterpret_cast<uint32_t*>(Olo + base0 + nl) = lo01;
                *reinterpret_cast<uint32_t*>(Ohi + base1 + nl) = h23;
                *reinterpret_cast<uint32_t*>(Olo + base1 + nl) = lo23;
            }
        }
    } else {
        float p0[16], p1[16];
        #pragma unroll
        for (int j = 0; j < 16; j++) { p0[j] = 0.f; p1[j] = 0.f; }
        #pragma unroll
        for (int mt = 0; mt < 2; mt++) {
            int co0 = co_base + mt * 16 + g, co1 = co0 + 8;
            float sc0 = gam[co0] * rsqrtf(var[co0] + 1e-5f);
            float sh0 = bet[co0] - mu[co0] * sc0;
            float sc1 = gam[co1] * rsqrtf(var[co1] + 1e-5f);
            float sh1 = bet[co1] - mu[co1] * sc1;
            float wa0 = w4[co0 * 8 + h], wb0 = w4[2048 + co0 * 8 + h];
            float wa1 = w4[co1 * 8 + h], wb1 = w4[2048 + co1 * 8 + h];
            #pragma unroll
            for (int nt = 0; nt < 8; nt++) {
                float y0 = fmaxf(fmaf(acc[mt][nt][0], sc0, sh0), 0.f);
                float y1 = fmaxf(fmaf(acc[mt][nt][1], sc0, sh0), 0.f);
                float y2 = fmaxf(fmaf(acc[mt][nt][2], sc1, sh1), 0.f);
                float y3 = fmaxf(fmaf(acc[mt][nt][3], sc1, sh1), 0.f);
                p0[nt * 2]     += y0 * wa0 + y2 * wa1;
                p0[nt * 2 + 1] += y1 * wa0 + y3 * wa1;
                p1[nt * 2]     += y0 * wb0 + y2 * wb1;
                p1[nt * 2 + 1] += y1 * wb0 + y3 * wb1;
            }
        }
        #pragma unroll
        for (int off = 4; off <= 16; off <<= 1) {
            #pragma unroll
            for (int j = 0; j < 16; j++) {
                p0[j] += __shfl_xor_sync(0xffffffffu, p0[j], off);
                p1[j] += __shfl_xor_sync(0xffffffffu, p1[j], off);
            }
        }
        if (g == 0) {
            #pragma unroll
            for (int j = 0; j < 16; j++) {
                int nl = wn * 64 + (j >> 1) * 8 + 2 * t + (j & 1);
                atomicAdd(&s_part[nl * 2],     p0[j]);
                atomicAdd(&s_part[nl * 2 + 1], p1[j]);
            }
        }
        __syncthreads();
        if (tid < 512) {
            int nl = tid >> 1, ch = tid & 1;
            atomicAdd(dout + (size_t)(b0 + nl) * 28 + w_pos * 2 + ch, s_part[tid]);
        }
    }
}

// ======================= host launch =======================
extern "C" void kernel_launch(void* const* d_in, const int* in_sizes, int n_in,
                              void* d_out, int out_size)
{
    (void)n_in;
    const float* x   = (const float*)d_in[0];
    const float* sig = (const float*)d_in[1];
    const float* w1  = (const float*)d_in[2];
    const float *w2, *w3, *w4;
    const float *g1,*b1,*m1,*v1,*g2,*b2,*m2,*v2,*g3,*b3,*m3,*v3;

    if (in_sizes[3] == 73728) {
        w2=(const float*)d_in[3];  w3=(const float*)d_in[4];  w4=(const float*)d_in[5];
        g1=(const float*)d_in[6];  b1=(const float*)d_in[7];  m1=(const float*)d_in[8];  v1=(const float*)d_in[9];
        g2=(const float*)d_in[10]; b2=(const float*)d_in[11]; m2=(const float*)d_in[12]; v2=(const float*)d_in[13];
        g3=(const float*)d_in[14]; b3=(const float*)d_in[15]; m3=(const float*)d_in[16]; v3=(const float*)d_in[17];
    } else {
        g1=(const float*)d_in[3];  b1=(const float*)d_in[4];  m1=(const float*)d_in[5];  v1=(const float*)d_in[6];
        w2=(const float*)d_in[7];
        g2=(const float*)d_in[8];  b2=(const float*)d_in[9];  m2=(const float*)d_in[10]; v2=(const float*)d_in[11];
        w3=(const float*)d_in[12];
        g3=(const float*)d_in[13]; b3=(const float*)d_in[14]; m3=(const float*)d_in[15]; v3=(const float*)d_in[16];
        w4=(const float*)d_in[17];
    }

    bf16 *a1hi, *a1lo, *a2hi, *a2lo, *w2hi, *w2lo, *w3hi, *w3lo;
    cudaGetSymbolAddress((void**)&a1hi, g_a1hi);
    cudaGetSymbolAddress((void**)&a1lo, g_a1lo);
    cudaGetSymbolAddress((void**)&a2hi, g_a2hi);
    cudaGetSymbolAddress((void**)&a2lo, g_a2lo);
    cudaGetSymbolAddress((void**)&w2hi, g_w2hi);
    cudaGetSymbolAddress((void**)&w2lo, g_w2lo);
    cudaGetSymbolAddress((void**)&w3hi, g_w3hi);
    cudaGetSymbolAddress((void**)&w3lo, g_w3lo);

    cudaFuncSetAttribute(conv_mma<34, 9, false>,
                         cudaFuncAttributeMaxDynamicSharedMemorySize, SMEM_TOT);
    cudaFuncSetAttribute(conv_mma<18, 18, true>,
                         cudaFuncAttributeMaxDynamicSharedMemorySize, SMEM_TOT);

    // 0) zero output accumulator (conv4 adds atomically)
    zero_out_kernel<<<(out_size + 1023) / 1024, 1024>>>((float*)d_out, out_size);
    // 1) input -> padded fp32 CHWN
    prep_input_kernel<<<896, 256>>>(x, sig);
    // 2) weight bf16 splits
    split_w_kernel<<<(73728 + 255) / 256, 256>>>(w2, w2hi, w2lo, 73728);
    split_w_kernel<<<(294912 + 255) / 256, 256>>>(w3, w3hi, w3lo, 294912);
    // 3) conv1 scalar -> a1
    conv1_kernel<<<dim3(14, 32, 2), 256>>>(w1, g1, b1, m1, v1);
    // 4) conv2 (mma.sync, pipelined) -> a2
    conv_mma<34, 9, false><<<dim3(112, 16, 1), 512, SMEM_TOT>>>(
        a1hi, a1lo, w2hi, w2lo, g2, b2, m2, v2, nullptr,
        a2hi, a2lo, nullptr, 18);
    // 5) conv3 (mma.sync, pipelined) + fused conv4 -> d_out
    conv_mma<18, 18, true><<<dim3(112, 8, 2), 512, SMEM_TOT>>>(
        a2hi, a2lo, w3hi, w3lo, g3, b3, m3, v3, w4,
        nullptr, nullptr, (float*)d_out, 0);
}

// round 9
// speedup vs baseline: 3.7336x; 1.0714x over previous
#include <cuda_runtime.h>
#include <cuda_bf16.h>
#include <cstdint>

typedef unsigned long long ull;
typedef __nv_bfloat16 bf16;

#define B_N 2048

// ---------------- device scratch (zero-init at load; pad cells never written) ----
__device__ float g_in0F[2 * 65 * 16 * 2048];                 // conv1 input, padded CHWN
__device__ bf16  g_a1hi[(size_t)64 * 34 * 16 * 2048];        // conv1 out hi
__device__ bf16  g_a1lo[(size_t)64 * 34 * 16 * 2048];        // conv1 out lo
__device__ bf16  g_a2hi[(size_t)128 * 18 * 16 * 2048];       // conv2 out hi
__device__ bf16  g_a2lo[(size_t)128 * 18 * 16 * 2048];       // conv2 out lo
__device__ bf16  g_w2hi[128 * 576],  g_w2lo[128 * 576];
__device__ bf16  g_w3hi[256 * 1152], g_w3lo[256 * 1152];

// ---------------- helpers ----------------
__device__ __forceinline__ uint32_t smem_u32(const void* p) {
    uint32_t a;
    asm("{ .reg .u64 t; cvta.to.shared.u64 t, %1; cvt.u32.u64 %0, t; }"
        : "=r"(a) : "l"(p));
    return a;
}
__device__ __forceinline__ ull pack2(float x) {
    ull r; asm("mov.b64 %0, {%1, %1};" : "=l"(r) : "f"(x)); return r;
}
__device__ __forceinline__ void fma2(ull &acc, ull a, ull b) {
    asm("fma.rn.f32x2 %0, %1, %2, %0;" : "+l"(acc) : "l"(a), "l"(b));
}
__device__ __forceinline__ float2 unpack2(ull v) {
    float2 r; asm("mov.b64 {%0, %1}, %2;" : "=f"(r.x), "=f"(r.y) : "l"(v)); return r;
}
__device__ __forceinline__ uint32_t cvt_bf16x2(float y0, float y1) {
    uint32_t r;
    asm("cvt.rn.bf16x2.f32 %0, %1, %2;" : "=r"(r) : "f"(y1), "f"(y0));
    return r;
}

// ldmatrix / mma.sync (base ISA)
__device__ __forceinline__ void ldsm4(uint32_t* r, uint32_t a) {
    asm volatile("ldmatrix.sync.aligned.m8n8.x4.shared.b16 {%0,%1,%2,%3}, [%4];"
        : "=r"(r[0]), "=r"(r[1]), "=r"(r[2]), "=r"(r[3]) : "r"(a));
}
__device__ __forceinline__ void ldsm2t(uint32_t* r, uint32_t a) {
    asm volatile("ldmatrix.sync.aligned.m8n8.x2.trans.shared.b16 {%0,%1}, [%2];"
        : "=r"(r[0]), "=r"(r[1]) : "r"(a));
}
__device__ __forceinline__ void mma16816(float* d, const uint32_t* a, const uint32_t* b) {
    asm volatile(
        "mma.sync.aligned.m16n8k16.row.col.f32.bf16.bf16.f32 "
        "{%0,%1,%2,%3}, {%4,%5,%6,%7}, {%8,%9}, {%0,%1,%2,%3};"
        : "+f"(d[0]), "+f"(d[1]), "+f"(d[2]), "+f"(d[3])
        : "r"(a[0]), "r"(a[1]), "r"(a[2]), "r"(a[3]), "r"(b[0]), "r"(b[1]));
}

// cp.async
#define CP_ASYNC16(dst, src) \
    asm volatile("cp.async.cg.shared.global [%0], [%1], 16;" :: "r"(dst), "l"(src))
#define CP_COMMIT() asm volatile("cp.async.commit_group;" ::: "memory")
#define CP_WAIT0()  asm volatile("cp.async.wait_group 0;" ::: "memory")
#define CP_WAIT1()  asm volatile("cp.async.wait_group 1;" ::: "memory")

// ======================= small prep kernels =======================
__global__ void zero_out_kernel(float* p, int n) {
    int i = blockIdx.x * 1024 + threadIdx.x;
    if (i < n) p[i] = 0.f;
}

// x,sigmas [B][64][14] -> g_in0F [2][65][16][B]
__global__ void prep_input_kernel(const float* __restrict__ x,
                                  const float* __restrict__ sig) {
    int fk = blockIdx.x;            // 0..895
    int f = fk / 14, k = fk % 14;
    int t = threadIdx.x;
    for (int it = 0; it < 8; it++) {
        int b = it * 256 + t;
        float xv = x[(size_t)b * 896 + fk];
        float sv = sig[(size_t)b * 896 + fk] * 10.0f;
        g_in0F[((size_t)(0 * 65 + f + 1) * 16 + k + 1) * B_N + b] = xv;
        g_in0F[((size_t)(1 * 65 + f + 1) * 16 + k + 1) * B_N + b] = sv;
    }
}

__global__ void split_w_kernel(const float* __restrict__ w, bf16* __restrict__ hi,
                               bf16* __restrict__ lo, int n) {
    int i = blockIdx.x * 256 + threadIdx.x;
    if (i >= n) return;
    float f = w[i];
    bf16 h = __float2bfloat16_rn(f);
    hi[i] = h;
    lo[i] = __float2bfloat16_rn(f - __bfloat162float(h));
}

// ======================= conv1 (scalar fp32 -> bf16 split CHWN) ===========
__global__ void __launch_bounds__(256, 2)
conv1_kernel(const float* __restrict__ w1,   // [64][2][3][3]
             const float* __restrict__ g1, const float* __restrict__ b1,
             const float* __restrict__ m1, const float* __restrict__ v1)
{
    __shared__ float sw[1152];
    const int w = blockIdx.x, h = blockIdx.y;
    const int t = threadIdx.x;
    for (int i = t; i < 1152; i += 256) sw[i] = w1[i];
    __syncthreads();

    const int b0 = (blockIdx.z * 256 + t) * 4;
    ull u[18][2];
    #pragma unroll
    for (int ci = 0; ci < 2; ci++)
        #pragma unroll
        for (int kh = 0; kh < 3; kh++)
            #pragma unroll
            for (int kw = 0; kw < 3; kw++) {
                int idx = ci * 9 + kh * 3 + kw;
                const ull* p = reinterpret_cast<const ull*>(
                    g_in0F + ((size_t)(ci * 65 + 2 * h + kh) * 16 + w + kw) * B_N + b0);
                u[idx][0] = p[0];
                u[idx][1] = p[1];
            }

    for (int co = 0; co < 64; co++) {
        ull a0 = 0ull, a1 = 0ull;
        #pragma unroll
        for (int idx = 0; idx < 18; idx++) {
            ull wv = pack2(sw[co * 18 + idx]);
            fma2(a0, u[idx][0], wv);
            fma2(a1, u[idx][1], wv);
        }
        float sc = __ldg(g1 + co) * rsqrtf(__ldg(v1 + co) + 1e-5f);
        float sh = __ldg(b1 + co) - __ldg(m1 + co) * sc;
        float2 p0 = unpack2(a0), p1 = unpack2(a1);
        float y0 = fmaxf(fmaf(p0.x, sc, sh), 0.f);
        float y1 = fmaxf(fmaf(p0.y, sc, sh), 0.f);
        float y2 = fmaxf(fmaf(p1.x, sc, sh), 0.f);
        float y3 = fmaxf(fmaf(p1.y, sc, sh), 0.f);
        uint32_t h01 = cvt_bf16x2(y0, y1), h23 = cvt_bf16x2(y2, y3);
        float l0 = y0 - __uint_as_float(h01 << 16);
        float l1 = y1 - __uint_as_float(h01 & 0xFFFF0000u);
        float l2 = y2 - __uint_as_float(h23 << 16);
        float l3 = y3 - __uint_as_float(h23 & 0xFFFF0000u);
        uint32_t lo01 = cvt_bf16x2(l0, l1), lo23 = cvt_bf16x2(l2, l3);
        size_t addr = ((size_t)(co * 34 + h + 1) * 16 + w + 1) * B_N + b0;
        *reinterpret_cast<uint32_t*>(g_a1hi + addr)     = h01;
        *reinterpret_cast<uint32_t*>(g_a1hi + addr + 2) = h23;
        *reinterpret_cast<uint32_t*>(g_a1lo + addr)     = lo01;
        *reinterpret_cast<uint32_t*>(g_a1lo + addr + 2) = lo23;
    }
}

// ======================= mma.sync conv GEMM v4 =======================
// CTA: D[128 co][128 n], K-chunk 32, 256 threads (8 warps, 4m x 2n),
// warp = 32co x 64n.  bf16 hi/lo 3-pass.  cp.async double-buffered.
// 2 CTAs/SM (76.8 KB smem, <=128 regs).  Grid: x = h (fastest, L2 reuse).
// Per-buffer: A hi [128][40bf16] @0, A lo @10240,
//             B hi [32][136bf16] @20480, B lo @29184.  BUF_SZ = 37888.
static constexpr int OFF_ALO_L = 10240;
static constexpr int OFF_BHI_L = 20480;
static constexpr int OFF_BLO_L = 29184;
static constexpr int BUF_SZ    = 37888;
static constexpr int OFF_PART  = 2 * BUF_SZ;        // 256 floats (FUSE4)
static constexpr int SMEM_TOT  = OFF_PART + 1024;   // 76800

template<int HPIN, int CHUNKS, bool FUSE4>
__global__ void __launch_bounds__(256, 2)
conv_mma(const bf16* __restrict__ Xhi, const bf16* __restrict__ Xlo,
         const bf16* __restrict__ Whi, const bf16* __restrict__ Wlo,
         const float* __restrict__ gam, const float* __restrict__ bet,
         const float* __restrict__ mu,  const float* __restrict__ var,
         const float* __restrict__ w4,
         bf16* __restrict__ Ohi, bf16* __restrict__ Olo,
         float* __restrict__ dout, int HP_OUT)
{
    constexpr int KTOT = CHUNKS * 32;
    extern __shared__ __align__(16) char smem[];
    const uint32_t smb = smem_u32(smem);
    float* s_part = reinterpret_cast<float*>(smem + OFF_PART);

    const int tid  = threadIdx.x;
    const int lane = tid & 31, wid = tid >> 5;
    const int wm = wid & 3, wn = wid >> 2;          // 4m x 2n warps
    const int g = lane >> 2, t = lane & 3;
    const int h  = blockIdx.x;                      // h fastest => L2 reuse of X
    const int n0 = blockIdx.y * 128;
    const int mtile = blockIdx.z;
    const int w_pos = n0 >> 11;
    const int b0    = n0 & 2047;

    if (FUSE4) s_part[tid] = 0.f;

    // ldmatrix lane addresses (offsets within a buffer)
    const int rA = lane & 15;
    const int kA = (lane >> 4) << 3;
    const uint32_t aOff0 = (uint32_t)((wm * 32 +  0 + rA) * 80 + kA * 2);
    const uint32_t aOff1 = (uint32_t)((wm * 32 + 16 + rA) * 80 + kA * 2);
    const uint32_t bOff  = (uint32_t)(OFF_BHI_L + (lane & 15) * 272 + wn * 128);

    float acc[2][8][4];
    #pragma unroll
    for (int mt = 0; mt < 2; mt++)
        #pragma unroll
        for (int nt = 0; nt < 8; nt++)
            #pragma unroll
            for (int i = 0; i < 4; i++) acc[mt][nt][i] = 0.f;

    // ---- async stage of chunk cc into buffer bufOff ----
    auto stage = [&](int cc, uint32_t bufOff) {
        // A: weights [128co][32k] hi+lo (64B data per row)
        #pragma unroll
        for (int it = 0; it < 2; it++) {
            int e = it * 256 + tid;                 // 0..511
            int row = e >> 2, q = e & 3;
            size_t go = (size_t)(mtile * 128 + row) * KTOT + cc * 32 + q * 8;
            uint32_t so = smb + bufOff + (uint32_t)(row * 80 + q * 16);
            CP_ASYNC16(so,             Whi + go);
            CP_ASYNC16(so + OFF_ALO_L, Wlo + go);
        }
        // B: acts [32k][128n] hi+lo (256B data per row)
        #pragma unroll
        for (int it = 0; it < 2; it++) {
            int e = it * 256 + tid;                 // 0..511
            int row = e >> 4, n16 = e & 15;
            int k = cc * 32 + row;
            int ci = k / 9;
            int r9 = k - ci * 9;
            int kh = r9 / 3;
            int kw = r9 - kh * 3;
            size_t go = ((size_t)(ci * HPIN + 2 * h + kh) * 16 + w_pos + kw) * B_N
                        + b0 + n16 * 8;
            uint32_t so = smb + bufOff + (uint32_t)(OFF_BHI_L + row * 272 + n16 * 16);
            CP_ASYNC16(so,                           Xhi + go);
            CP_ASYNC16(so + (OFF_BLO_L - OFF_BHI_L), Xlo + go);
        }
        CP_COMMIT();
    };

    stage(0, 0);

    #pragma unroll 1
    for (int c = 0; c < CHUNKS; c++) {
        const uint32_t cur = (c & 1) ? BUF_SZ : 0;
        if (c + 1 < CHUNKS) {
            stage(c + 1, cur ^ BUF_SZ);
            CP_WAIT1();
        } else {
            CP_WAIT0();
        }
        __syncthreads();

        const uint32_t aHi0 = smb + cur + aOff0;
        const uint32_t aHi1 = smb + cur + aOff1;
        const uint32_t bA   = smb + cur + bOff;
        #pragma unroll
        for (int ks = 0; ks < 2; ks++) {
            uint32_t Ah0[4], Ah1[4], Al0[4], Al1[4];
            ldsm4(Ah0, aHi0 + ks * 32);
            ldsm4(Ah1, aHi1 + ks * 32);
            ldsm4(Al0, aHi0 + OFF_ALO_L + ks * 32);
            ldsm4(Al1, aHi1 + OFF_ALO_L + ks * 32);
            #pragma unroll
            for (int nt = 0; nt < 8; nt++) {
                uint32_t bh[2], bl[2];
                ldsm2t(bh, bA + ks * 4352 + nt * 16);
                ldsm2t(bl, bA + (OFF_BLO_L - OFF_BHI_L) + ks * 4352 + nt * 16);
                mma16816(acc[0][nt], Ah0, bh);
                mma16816(acc[0][nt], Ah0, bl);
                mma16816(acc[0][nt], Al0, bh);
                mma16816(acc[1][nt], Ah1, bh);
                mma16816(acc[1][nt], Ah1, bl);
                mma16816(acc[1][nt], Al1, bh);
            }
        }
        __syncthreads();
    }

    // ======================= epilogue =======================
    const int co_base = mtile * 128 + wm * 32;
    if (!FUSE4) {
        #pragma unroll
        for (int mt = 0; mt < 2; mt++) {
            int co0 = co_base + mt * 16 + g, co1 = co0 + 8;
            float sc0 = gam[co0] * rsqrtf(var[co0] + 1e-5f);
            float sh0 = bet[co0] - mu[co0] * sc0;
            float sc1 = gam[co1] * rsqrtf(var[co1] + 1e-5f);
            float sh1 = bet[co1] - mu[co1] * sc1;
            size_t base0 = ((size_t)(co0 * HP_OUT + h + 1) * 16 + w_pos + 1) * B_N + b0;
            size_t base1 = ((size_t)(co1 * HP_OUT + h + 1) * 16 + w_pos + 1) * B_N + b0;
            #pragma unroll
            for (int nt = 0; nt < 8; nt++) {
                int nl = wn * 64 + nt * 8 + 2 * t;
                float y0 = fmaxf(fmaf(acc[mt][nt][0], sc0, sh0), 0.f);
                float y1 = fmaxf(fmaf(acc[mt][nt][1], sc0, sh0), 0.f);
                float y2 = fmaxf(fmaf(acc[mt][nt][2], sc1, sh1), 0.f);
                float y3 = fmaxf(fmaf(acc[mt][nt][3], sc1, sh1), 0.f);
                uint32_t h01 = cvt_bf16x2(y0, y1);
                float l0 = y0 - __uint_as_float(h01 << 16);
                float l1 = y1 - __uint_as_float(h01 & 0xFFFF0000u);
                uint32_t lo01 = cvt_bf16x2(l0, l1);
                uint32_t h23 = cvt_bf16x2(y2, y3);
                float l2 = y2 - __uint_as_float(h23 << 16);
                float l3 = y3 - __uint_as_float(h23 & 0xFFFF0000u);
                uint32_t lo23 = cvt_bf16x2(l2, l3);
                *reinterpret_cast<uint32_t*>(Ohi + base0 + nl) = h01;
                *reinterpret_cast<uint32_t*>(Olo + base0 + nl) = lo01;
                *reinterpret_cast<uint32_t*>(Ohi + base1 + nl) = h23;
                *reinterpret_cast<uint32_t*>(Olo + base1 + nl) = lo23;
            }
        }
    } else {
        float p0[16], p1[16];
        #pragma unroll
        for (int j = 0; j < 16; j++) { p0[j] = 0.f; p1[j] = 0.f; }
        #pragma unroll
        for (int mt = 0; mt < 2; mt++) {
            int co0 = co_base + mt * 16 + g, co1 = co0 + 8;
            float sc0 = gam[co0] * rsqrtf(var[co0] + 1e-5f);
            float sh0 = bet[co0] - mu[co0] * sc0;
            float sc1 = gam[co1] * rsqrtf(var[co1] + 1e-5f);
            float sh1 = bet[co1] - mu[co1] * sc1;
            float wa0 = w4[co0 * 8 + h], wb0 = w4[2048 + co0 * 8 + h];
            float wa1 = w4[co1 * 8 + h], wb1 = w4[2048 + co1 * 8 + h];
            #pragma unroll
            for (int nt = 0; nt < 8; nt++) {
                float y0 = fmaxf(fmaf(acc[mt][nt][0], sc0, sh0), 0.f);
                float y1 = fmaxf(fmaf(acc[mt][nt][1], sc0, sh0), 0.f);
                float y2 = fmaxf(fmaf(acc[mt][nt][2], sc1, sh1), 0.f);
                float y3 = fmaxf(fmaf(acc[mt][nt][3], sc1, sh1), 0.f);
                p0[nt * 2]     += y0 * wa0 + y2 * wa1;
                p0[nt * 2 + 1] += y1 * wa0 + y3 * wa1;
                p1[nt * 2]     += y0 * wb0 + y2 * wb1;
                p1[nt * 2 + 1] += y1 * wb0 + y3 * wb1;
            }
        }
        #pragma unroll
        for (int off = 4; off <= 16; off <<= 1) {
            #pragma unroll
            for (int j = 0; j < 16; j++) {
                p0[j] += __shfl_xor_sync(0xffffffffu, p0[j], off);
                p1[j] += __shfl_xor_sync(0xffffffffu, p1[j], off);
            }
        }
        if (g == 0) {
            #pragma unroll
            for (int j = 0; j < 16; j++) {
                int nl = wn * 64 + (j >> 1) * 8 + 2 * t + (j & 1);
                atomicAdd(&s_part[nl * 2],     p0[j]);
                atomicAdd(&s_part[nl * 2 + 1], p1[j]);
            }
        }
        __syncthreads();
        {
            int nl = tid >> 1, ch = tid & 1;
            atomicAdd(dout + (size_t)(b0 + nl) * 28 + w_pos * 2 + ch, s_part[tid]);
        }
    }
}

// ======================= host launch =======================
extern "C" void kernel_launch(void* const* d_in, const int* in_sizes, int n_in,
                              void* d_out, int out_size)
{
    (void)n_in;
    const float* x   = (const float*)d_in[0];
    const float* sig = (const float*)d_in[1];
    const float* w1  = (const float*)d_in[2];
    const float *w2, *w3, *w4;
    const float *g1,*b1,*m1,*v1,*g2,*b2,*m2,*v2,*g3,*b3,*m3,*v3;

    if (in_sizes[3] == 73728) {
        w2=(const float*)d_in[3];  w3=(const float*)d_in[4];  w4=(const float*)d_in[5];
        g1=(const float*)d_in[6];  b1=(const float*)d_in[7];  m1=(const float*)d_in[8];  v1=(const float*)d_in[9];
        g2=(const float*)d_in[10]; b2=(const float*)d_in[11]; m2=(const float*)d_in[12]; v2=(const float*)d_in[13];
        g3=(const float*)d_in[14]; b3=(const float*)d_in[15]; m3=(const float*)d_in[16]; v3=(const float*)d_in[17];
    } else {
        g1=(const float*)d_in[3];  b1=(const float*)d_in[4];  m1=(const float*)d_in[5];  v1=(const float*)d_in[6];
        w2=(const float*)d_in[7];
        g2=(const float*)d_in[8];  b2=(const float*)d_in[9];  m2=(const float*)d_in[10]; v2=(const float*)d_in[11];
        w3=(const float*)d_in[12];
        g3=(const float*)d_in[13]; b3=(const float*)d_in[14]; m3=(const float*)d_in[15]; v3=(const float*)d_in[16];
        w4=(const float*)d_in[17];
    }

    bf16 *a1hi, *a1lo, *a2hi, *a2lo, *w2hi, *w2lo, *w3hi, *w3lo;
    cudaGetSymbolAddress((void**)&a1hi, g_a1hi);
    cudaGetSymbolAddress((void**)&a1lo, g_a1lo);
    cudaGetSymbolAddress((void**)&a2hi, g_a2hi);
    cudaGetSymbolAddress((void**)&a2lo, g_a2lo);
    cudaGetSymbolAddress((void**)&w2hi, g_w2hi);
    cudaGetSymbolAddress((void**)&w2lo, g_w2lo);
    cudaGetSymbolAddress((void**)&w3hi, g_w3hi);
    cudaGetSymbolAddress((void**)&w3lo, g_w3lo);

    cudaFuncSetAttribute(conv_mma<34, 18, false>,
                         cudaFuncAttributeMaxDynamicSharedMemorySize, SMEM_TOT);
    cudaFuncSetAttribute(conv_mma<18, 36, true>,
                         cudaFuncAttributeMaxDynamicSharedMemorySize, SMEM_TOT);

    // 0) zero output accumulator (conv4 adds atomically)
    zero_out_kernel<<<(out_size + 1023) / 1024, 1024>>>((float*)d_out, out_size);
    // 1) input -> padded fp32 CHWN
    prep_input_kernel<<<896, 256>>>(x, sig);
    // 2) weight bf16 splits
    split_w_kernel<<<(73728 + 255) / 256, 256>>>(w2, w2hi, w2lo, 73728);
    split_w_kernel<<<(294912 + 255) / 256, 256>>>(w3, w3hi, w3lo, 294912);
    // 3) conv1 scalar -> a1
    conv1_kernel<<<dim3(14, 32, 2), 256>>>(w1, g1, b1, m1, v1);
    // 4) conv2 (mma.sync, pipelined, 2 CTA/SM) -> a2
    conv_mma<34, 18, false><<<dim3(16, 224, 1), 256, SMEM_TOT>>>(
        a1hi, a1lo, w2hi, w2lo, g2, b2, m2, v2, nullptr,
        a2hi, a2lo, nullptr, 18);
    // 5) conv3 (mma.sync, pipelined) + fused conv4 -> d_out
    conv_mma<18, 36, true><<<dim3(8, 224, 2), 256, SMEM_TOT>>>(
        a2hi, a2lo, w3hi, w3lo, g3, b3, m3, v3, w4,
        nullptr, nullptr, (float*)d_out, 0);
}

// round 10
// speedup vs baseline: 5.4760x; 1.4667x over previous
#include <cuda_runtime.h>
#include <cuda_fp16.h>
#include <cstdint>

typedef unsigned long long ull;

#define B_N 2048

// ---------------- device scratch (zero-init at load; pad cells never written) ----
__device__ float  g_in0F[2 * 65 * 16 * 2048];                // conv1 input, padded CHWN
__device__ __half g_a1[(size_t)64 * 34 * 16 * 2048];         // conv1 out (fp16)
__device__ __half g_a2[(size_t)128 * 18 * 16 * 2048];        // conv2 out (fp16)
__device__ __half g_w2hi[128 * 576],  g_w2lo[128 * 576];
__device__ __half g_w3hi[256 * 1152], g_w3lo[256 * 1152];

// ---------------- helpers ----------------
__device__ __forceinline__ uint32_t smem_u32(const void* p) {
    uint32_t a;
    asm("{ .reg .u64 t; cvta.to.shared.u64 t, %1; cvt.u32.u64 %0, t; }"
        : "=r"(a) : "l"(p));
    return a;
}
__device__ __forceinline__ ull pack2(float x) {
    ull r; asm("mov.b64 %0, {%1, %1};" : "=l"(r) : "f"(x)); return r;
}
__device__ __forceinline__ void fma2(ull &acc, ull a, ull b) {
    asm("fma.rn.f32x2 %0, %1, %2, %0;" : "+l"(acc) : "l"(a), "l"(b));
}
__device__ __forceinline__ float2 unpack2(ull v) {
    float2 r; asm("mov.b64 {%0, %1}, %2;" : "=f"(r.x), "=f"(r.y) : "l"(v)); return r;
}
__device__ __forceinline__ uint32_t f16x2(float y0, float y1) {
    __half2 h = __floats2half2_rn(y0, y1);      // y0 -> low half
    return *reinterpret_cast<uint32_t*>(&h);
}

// ldmatrix / mma.sync (base ISA)
__device__ __forceinline__ void ldsm4(uint32_t* r, uint32_t a) {
    asm volatile("ldmatrix.sync.aligned.m8n8.x4.shared.b16 {%0,%1,%2,%3}, [%4];"
        : "=r"(r[0]), "=r"(r[1]), "=r"(r[2]), "=r"(r[3]) : "r"(a));
}
__device__ __forceinline__ void ldsm2t(uint32_t* r, uint32_t a) {
    asm volatile("ldmatrix.sync.aligned.m8n8.x2.trans.shared.b16 {%0,%1}, [%2];"
        : "=r"(r[0]), "=r"(r[1]) : "r"(a));
}
__device__ __forceinline__ void mma16816(float* d, const uint32_t* a, const uint32_t* b) {
    asm volatile(
        "mma.sync.aligned.m16n8k16.row.col.f32.f16.f16.f32 "
        "{%0,%1,%2,%3}, {%4,%5,%6,%7}, {%8,%9}, {%0,%1,%2,%3};"
        : "+f"(d[0]), "+f"(d[1]), "+f"(d[2]), "+f"(d[3])
        : "r"(a[0]), "r"(a[1]), "r"(a[2]), "r"(a[3]), "r"(b[0]), "r"(b[1]));
}

// cp.async
#define CP_ASYNC16(dst, src) \
    asm volatile("cp.async.cg.shared.global [%0], [%1], 16;" :: "r"(dst), "l"(src))
#define CP_COMMIT() asm volatile("cp.async.commit_group;" ::: "memory")
#define CP_WAIT0()  asm volatile("cp.async.wait_group 0;" ::: "memory")
#define CP_WAIT1()  asm volatile("cp.async.wait_group 1;" ::: "memory")

// ======================= small prep kernels =======================
__global__ void zero_out_kernel(float* p, int n) {
    int i = blockIdx.x * 1024 + threadIdx.x;
    if (i < n) p[i] = 0.f;
}

// x,sigmas [B][64][14] -> g_in0F [2][65][16][B]
__global__ void prep_input_kernel(const float* __restrict__ x,
                                  const float* __restrict__ sig) {
    int fk = blockIdx.x;            // 0..895
    int f = fk / 14, k = fk % 14;
    int t = threadIdx.x;
    for (int it = 0; it < 8; it++) {
        int b = it * 256 + t;
        float xv = x[(size_t)b * 896 + fk];
        float sv = sig[(size_t)b * 896 + fk] * 10.0f;
        g_in0F[((size_t)(0 * 65 + f + 1) * 16 + k + 1) * B_N + b] = xv;
        g_in0F[((size_t)(1 * 65 + f + 1) * 16 + k + 1) * B_N + b] = sv;
    }
}

// fp32 weights -> fp16 hi/lo limbs (exact to ~2^-22)
__global__ void split_w_kernel(const float* __restrict__ w, __half* __restrict__ hi,
                               __half* __restrict__ lo, int n) {
    int i = blockIdx.x * 256 + threadIdx.x;
    if (i >= n) return;
    float f = w[i];
    __half h = __float2half_rn(f);
    hi[i] = h;
    lo[i] = __float2half_rn(f - __half2float(h));
}

// ======================= conv1 (scalar fp32 -> fp16 CHWN) ===========
__global__ void __launch_bounds__(256, 2)
conv1_kernel(const float* __restrict__ w1,   // [64][2][3][3]
             const float* __restrict__ g1, const float* __restrict__ b1,
             const float* __restrict__ m1, const float* __restrict__ v1)
{
    __shared__ float sw[1152];
    const int w = blockIdx.x, h = blockIdx.y;
    const int t = threadIdx.x;
    for (int i = t; i < 1152; i += 256) sw[i] = w1[i];
    __syncthreads();

    const int b0 = (blockIdx.z * 256 + t) * 4;
    ull u[18][2];
    #pragma unroll
    for (int ci = 0; ci < 2; ci++)
        #pragma unroll
        for (int kh = 0; kh < 3; kh++)
            #pragma unroll
            for (int kw = 0; kw < 3; kw++) {
                int idx = ci * 9 + kh * 3 + kw;
                const ull* p = reinterpret_cast<const ull*>(
                    g_in0F + ((size_t)(ci * 65 + 2 * h + kh) * 16 + w + kw) * B_N + b0);
                u[idx][0] = p[0];
                u[idx][1] = p[1];
            }

    for (int co = 0; co < 64; co++) {
        ull a0 = 0ull, a1 = 0ull;
        #pragma unroll
        for (int idx = 0; idx < 18; idx++) {
            ull wv = pack2(sw[co * 18 + idx]);
            fma2(a0, u[idx][0], wv);
            fma2(a1, u[idx][1], wv);
        }
        float sc = __ldg(g1 + co) * rsqrtf(__ldg(v1 + co) + 1e-5f);
        float sh = __ldg(b1 + co) - __ldg(m1 + co) * sc;
        float2 p0 = unpack2(a0), p1 = unpack2(a1);
        float y0 = fmaxf(fmaf(p0.x, sc, sh), 0.f);
        float y1 = fmaxf(fmaf(p0.y, sc, sh), 0.f);
        float y2 = fmaxf(fmaf(p1.x, sc, sh), 0.f);
        float y3 = fmaxf(fmaf(p1.y, sc, sh), 0.f);
        size_t addr = ((size_t)(co * 34 + h + 1) * 16 + w + 1) * B_N + b0;
        *reinterpret_cast<uint32_t*>(g_a1 + addr)     = f16x2(y0, y1);
        *reinterpret_cast<uint32_t*>(g_a1 + addr + 2) = f16x2(y2, y3);
    }
}

// ======================= mma.sync conv GEMM v5 (fp16, 2-pass) ============
// CTA: D[128 co][128 n], K-chunk 32, 256 threads (8 warps, 4m x 2n).
// Weights fp16 hi/lo (2 passes), activations single fp16.
// cp.async double-buffered; 2+ CTAs/SM.  Grid: x = h (L2 reuse of X).
// Per-buffer: A hi [128][40h] @0, A lo @10240, B [32][136h] @20480.
static constexpr int OFF_ALO_L = 10240;
static constexpr int OFF_B_L   = 20480;
static constexpr int BUF_SZ    = 29184;
static constexpr int OFF_PART  = 2 * BUF_SZ;        // 256 floats (FUSE4)
static constexpr int SMEM_TOT  = OFF_PART + 1024;   // 59392

template<int HPIN, int CHUNKS, bool FUSE4>
__global__ void __launch_bounds__(256, 2)
conv_mma(const __half* __restrict__ X,
         const __half* __restrict__ Whi, const __half* __restrict__ Wlo,
         const float* __restrict__ gam, const float* __restrict__ bet,
         const float* __restrict__ mu,  const float* __restrict__ var,
         const float* __restrict__ w4,
         __half* __restrict__ O,
         float* __restrict__ dout, int HP_OUT)
{
    constexpr int KTOT = CHUNKS * 32;
    extern __shared__ __align__(16) char smem[];
    const uint32_t smb = smem_u32(smem);
    float* s_part = reinterpret_cast<float*>(smem + OFF_PART);

    const int tid  = threadIdx.x;
    const int lane = tid & 31, wid = tid >> 5;
    const int wm = wid & 3, wn = wid >> 2;          // 4m x 2n warps
    const int g = lane >> 2, t = lane & 3;
    const int h  = blockIdx.x;                      // h fastest => L2 reuse of X
    const int n0 = blockIdx.y * 128;
    const int mtile = blockIdx.z;
    const int w_pos = n0 >> 11;
    const int b0    = n0 & 2047;

    if (FUSE4) s_part[tid] = 0.f;

    // ldmatrix lane addresses (offsets within a buffer)
    const int rA = lane & 15;
    const int kA = (lane >> 4) << 3;
    const uint32_t aOff0 = (uint32_t)((wm * 32 +  0 + rA) * 80 + kA * 2);
    const uint32_t aOff1 = (uint32_t)((wm * 32 + 16 + rA) * 80 + kA * 2);
    const uint32_t bOff  = (uint32_t)(OFF_B_L + (lane & 15) * 272 + wn * 128);

    float acc[2][8][4];
    #pragma unroll
    for (int mt = 0; mt < 2; mt++)
        #pragma unroll
        for (int nt = 0; nt < 8; nt++)
            #pragma unroll
            for (int i = 0; i < 4; i++) acc[mt][nt][i] = 0.f;

    // ---- async stage of chunk cc into buffer bufOff ----
    auto stage = [&](int cc, uint32_t bufOff) {
        // A: weights [128co][32k] hi+lo (64B data per row, pitch 80B)
        #pragma unroll
        for (int it = 0; it < 2; it++) {
            int e = it * 256 + tid;                 // 0..511
            int row = e >> 2, q = e & 3;
            size_t go = (size_t)(mtile * 128 + row) * KTOT + cc * 32 + q * 8;
            uint32_t so = smb + bufOff + (uint32_t)(row * 80 + q * 16);
            CP_ASYNC16(so,             Whi + go);
            CP_ASYNC16(so + OFF_ALO_L, Wlo + go);
        }
        // B: acts [32k][128n] fp16 (256B data per row, pitch 272B)
        #pragma unroll
        for (int it = 0; it < 2; it++) {
            int e = it * 256 + tid;                 // 0..511
            int row = e >> 4, n16 = e & 15;
            int k = cc * 32 + row;
            int ci = k / 9;
            int r9 = k - ci * 9;
            int kh = r9 / 3;
            int kw = r9 - kh * 3;
            size_t go = ((size_t)(ci * HPIN + 2 * h + kh) * 16 + w_pos + kw) * B_N
                        + b0 + n16 * 8;
            uint32_t so = smb + bufOff + (uint32_t)(OFF_B_L + row * 272 + n16 * 16);
            CP_ASYNC16(so, X + go);
        }
        CP_COMMIT();
    };

    stage(0, 0);

    #pragma unroll 1
    for (int c = 0; c < CHUNKS; c++) {
        const uint32_t cur = (c & 1) ? BUF_SZ : 0;
        if (c + 1 < CHUNKS) {
            stage(c + 1, cur ^ BUF_SZ);
            CP_WAIT1();
        } else {
            CP_WAIT0();
        }
        __syncthreads();

        const uint32_t aHi0 = smb + cur + aOff0;
        const uint32_t aHi1 = smb + cur + aOff1;
        const uint32_t bA   = smb + cur + bOff;
        #pragma unroll
        for (int ks = 0; ks < 2; ks++) {
            uint32_t Ah0[4], Ah1[4], Al0[4], Al1[4];
            ldsm4(Ah0, aHi0 + ks * 32);
            ldsm4(Ah1, aHi1 + ks * 32);
            ldsm4(Al0, aHi0 + OFF_ALO_L + ks * 32);
            ldsm4(Al1, aHi1 + OFF_ALO_L + ks * 32);
            #pragma unroll
            for (int nt = 0; nt < 8; nt++) {
                uint32_t bh[2];
                ldsm2t(bh, bA + ks * 4352 + nt * 16);
                mma16816(acc[0][nt], Ah0, bh);
                mma16816(acc[0][nt], Al0, bh);
                mma16816(acc[1][nt], Ah1, bh);
                mma16816(acc[1][nt], Al1, bh);
            }
        }
        __syncthreads();
    }

    // ======================= epilogue =======================
    const int co_base = mtile * 128 + wm * 32;
    if (!FUSE4) {
        #pragma unroll
        for (int mt = 0; mt < 2; mt++) {
            int co0 = co_base + mt * 16 + g, co1 = co0 + 8;
            float sc0 = gam[co0] * rsqrtf(var[co0] + 1e-5f);
            float sh0 = bet[co0] - mu[co0] * sc0;
            float sc1 = gam[co1] * rsqrtf(var[co1] + 1e-5f);
            float sh1 = bet[co1] - mu[co1] * sc1;
            size_t base0 = ((size_t)(co0 * HP_OUT + h + 1) * 16 + w_pos + 1) * B_N + b0;
            size_t base1 = ((size_t)(co1 * HP_OUT + h + 1) * 16 + w_pos + 1) * B_N + b0;
            #pragma unroll
            for (int nt = 0; nt < 8; nt++) {
                int nl = wn * 64 + nt * 8 + 2 * t;
                float y0 = fmaxf(fmaf(acc[mt][nt][0], sc0, sh0), 0.f);
                float y1 = fmaxf(fmaf(acc[mt][nt][1], sc0, sh0), 0.f);
                float y2 = fmaxf(fmaf(acc[mt][nt][2], sc1, sh1), 0.f);
                float y3 = fmaxf(fmaf(acc[mt][nt][3], sc1, sh1), 0.f);
                *reinterpret_cast<uint32_t*>(O + base0 + nl) = f16x2(y0, y1);
                *reinterpret_cast<uint32_t*>(O + base1 + nl) = f16x2(y2, y3);
            }
        }
    } else {
        float p0[16], p1[16];
        #pragma unroll
        for (int j = 0; j < 16; j++) { p0[j] = 0.f; p1[j] = 0.f; }
        #pragma unroll
        for (int mt = 0; mt < 2; mt++) {
            int co0 = co_base + mt * 16 + g, co1 = co0 + 8;
            float sc0 = gam[co0] * rsqrtf(var[co0] + 1e-5f);
            float sh0 = bet[co0] - mu[co0] * sc0;
            float sc1 = gam[co1] * rsqrtf(var[co1] + 1e-5f);
            float sh1 = bet[co1] - mu[co1] * sc1;
            float wa0 = w4[co0 * 8 + h], wb0 = w4[2048 + co0 * 8 + h];
            float wa1 = w4[co1 * 8 + h], wb1 = w4[2048 + co1 * 8 + h];
            #pragma unroll
            for (int nt = 0; nt < 8; nt++) {
                float y0 = fmaxf(fmaf(acc[mt][nt][0], sc0, sh0), 0.f);
                float y1 = fmaxf(fmaf(acc[mt][nt][1], sc0, sh0), 0.f);
                float y2 = fmaxf(fmaf(acc[mt][nt][2], sc1, sh1), 0.f);
                float y3 = fmaxf(fmaf(acc[mt][nt][3], sc1, sh1), 0.f);
                p0[nt * 2]     += y0 * wa0 + y2 * wa1;
                p0[nt * 2 + 1] += y1 * wa0 + y3 * wa1;
                p1[nt * 2]     += y0 * wb0 + y2 * wb1;
                p1[nt * 2 + 1] += y1 * wb0 + y3 * wb1;
            }
        }
        #pragma unroll
        for (int off = 4; off <= 16; off <<= 1) {
            #pragma unroll
            for (int j = 0; j < 16; j++) {
                p0[j] += __shfl_xor_sync(0xffffffffu, p0[j], off);
                p1[j] += __shfl_xor_sync(0xffffffffu, p1[j], off);
            }
        }
        if (g == 0) {
            #pragma unroll
            for (int j = 0; j < 16; j++) {
                int nl = wn * 64 + (j >> 1) * 8 + 2 * t + (j & 1);
                atomicAdd(&s_part[nl * 2],     p0[j]);
                atomicAdd(&s_part[nl * 2 + 1], p1[j]);
            }
        }
        __syncthreads();
        {
            int nl = tid >> 1, ch = tid & 1;
            atomicAdd(dout + (size_t)(b0 + nl) * 28 + w_pos * 2 + ch, s_part[tid]);
        }
    }
}

// ======================= host launch =======================
extern "C" void kernel_launch(void* const* d_in, const int* in_sizes, int n_in,
                              void* d_out, int out_size)
{
    (void)n_in;
    const float* x   = (const float*)d_in[0];
    const float* sig = (const float*)d_in[1];
    const float* w1  = (const float*)d_in[2];
    const float *w2, *w3, *w4;
    const float *g1,*b1,*m1,*v1,*g2,*b2,*m2,*v2,*g3,*b3,*m3,*v3;

    if (in_sizes[3] == 73728) {
        w2=(const float*)d_in[3];  w3=(const float*)d_in[4];  w4=(const float*)d_in[5];
        g1=(const float*)d_in[6];  b1=(const float*)d_in[7];  m1=(const float*)d_in[8];  v1=(const float*)d_in[9];
        g2=(const float*)d_in[10]; b2=(const float*)d_in[11]; m2=(const float*)d_in[12]; v2=(const float*)d_in[13];
        g3=(const float*)d_in[14]; b3=(const float*)d_in[15]; m3=(const float*)d_in[16]; v3=(const float*)d_in[17];
    } else {
        g1=(const float*)d_in[3];  b1=(const float*)d_in[4];  m1=(const float*)d_in[5];  v1=(const float*)d_in[6];
        w2=(const float*)d_in[7];
        g2=(const float*)d_in[8];  b2=(const float*)d_in[9];  m2=(const float*)d_in[10]; v2=(const float*)d_in[11];
        w3=(const float*)d_in[12];
        g3=(const float*)d_in[13]; b3=(const float*)d_in[14]; m3=(const float*)d_in[15]; v3=(const float*)d_in[16];
        w4=(const float*)d_in[17];
    }

    __half *a1, *a2, *w2hi, *w2lo, *w3hi, *w3lo;
    cudaGetSymbolAddress((void**)&a1, g_a1);
    cudaGetSymbolAddress((void**)&a2, g_a2);
    cudaGetSymbolAddress((void**)&w2hi, g_w2hi);
    cudaGetSymbolAddress((void**)&w2lo, g_w2lo);
    cudaGetSymbolAddress((void**)&w3hi, g_w3hi);
    cudaGetSymbolAddress((void**)&w3lo, g_w3lo);

    cudaFuncSetAttribute(conv_mma<34, 18, false>,
                         cudaFuncAttributeMaxDynamicSharedMemorySize, SMEM_TOT);
    cudaFuncSetAttribute(conv_mma<18, 36, true>,
                         cudaFuncAttributeMaxDynamicSharedMemorySize, SMEM_TOT);

    // 0) zero output accumulator (conv4 adds atomically)
    zero_out_kernel<<<(out_size + 1023) / 1024, 1024>>>((float*)d_out, out_size);
    // 1) input -> padded fp32 CHWN
    prep_input_kernel<<<896, 256>>>(x, sig);
    // 2) weight fp16 hi/lo splits
    split_w_kernel<<<(73728 + 255) / 256, 256>>>(w2, w2hi, w2lo, 73728);
    split_w_kernel<<<(294912 + 255) / 256, 256>>>(w3, w3hi, w3lo, 294912);
    // 3) conv1 scalar -> a1 (fp16 CHWN)
    conv1_kernel<<<dim3(14, 32, 2), 256>>>(w1, g1, b1, m1, v1);
    // 4) conv2 (fp16 2-pass mma, pipelined) -> a2
    conv_mma<34, 18, false><<<dim3(16, 224, 1), 256, SMEM_TOT>>>(
        a1, w2hi, w2lo, g2, b2, m2, v2, nullptr, a2, nullptr, 18);
    // 5) conv3 (fp16 2-pass mma) + fused conv4 -> d_out
    conv_mma<18, 36, true><<<dim3(8, 224, 2), 256, SMEM_TOT>>>(
        a2, w3hi, w3lo, g3, b3, m3, v3, w4, nullptr, (float*)d_out, 0);
}

// round 11
// speedup vs baseline: 8.1847x; 1.4946x over previous
#include <cuda_runtime.h>
#include <cuda_fp16.h>
#include <cstdint>

typedef unsigned long long ull;

#define B_N 2048

// ---------------- device scratch (zero-init at load; pad cells never written) ----
__device__ float  g_in0F[2 * 65 * 16 * 2048];                // conv1 input, padded CHWN
__device__ __half g_a1[(size_t)64 * 34 * 16 * 2048];         // conv1 out (fp16)
__device__ __half g_a2[(size_t)128 * 18 * 16 * 2048];        // conv2 out (fp16)
__device__ __half g_w2[128 * 576];
__device__ __half g_w3[256 * 1152];

// ---------------- helpers ----------------
__device__ __forceinline__ uint32_t smem_u32(const void* p) {
    uint32_t a;
    asm("{ .reg .u64 t; cvta.to.shared.u64 t, %1; cvt.u32.u64 %0, t; }"
        : "=r"(a) : "l"(p));
    return a;
}
__device__ __forceinline__ ull pack2(float x) {
    ull r; asm("mov.b64 %0, {%1, %1};" : "=l"(r) : "f"(x)); return r;
}
__device__ __forceinline__ void fma2(ull &acc, ull a, ull b) {
    asm("fma.rn.f32x2 %0, %1, %2, %0;" : "+l"(acc) : "l"(a), "l"(b));
}
__device__ __forceinline__ float2 unpack2(ull v) {
    float2 r; asm("mov.b64 {%0, %1}, %2;" : "=f"(r.x), "=f"(r.y) : "l"(v)); return r;
}
__device__ __forceinline__ uint32_t f16x2(float y0, float y1) {
    __half2 h = __floats2half2_rn(y0, y1);      // y0 -> low half
    return *reinterpret_cast<uint32_t*>(&h);
}

// ldmatrix / mma.sync (base ISA)
__device__ __forceinline__ void ldsm4(uint32_t* r, uint32_t a) {
    asm volatile("ldmatrix.sync.aligned.m8n8.x4.shared.b16 {%0,%1,%2,%3}, [%4];"
        : "=r"(r[0]), "=r"(r[1]), "=r"(r[2]), "=r"(r[3]) : "r"(a));
}
__device__ __forceinline__ void ldsm2t(uint32_t* r, uint32_t a) {
    asm volatile("ldmatrix.sync.aligned.m8n8.x2.trans.shared.b16 {%0,%1}, [%2];"
        : "=r"(r[0]), "=r"(r[1]) : "r"(a));
}
__device__ __forceinline__ void mma16816(float* d, const uint32_t* a, const uint32_t* b) {
    asm volatile(
        "mma.sync.aligned.m16n8k16.row.col.f32.f16.f16.f32 "
        "{%0,%1,%2,%3}, {%4,%5,%6,%7}, {%8,%9}, {%0,%1,%2,%3};"
        : "+f"(d[0]), "+f"(d[1]), "+f"(d[2]), "+f"(d[3])
        : "r"(a[0]), "r"(a[1]), "r"(a[2]), "r"(a[3]), "r"(b[0]), "r"(b[1]));
}

// cp.async
#define CP_ASYNC16(dst, src) \
    asm volatile("cp.async.cg.shared.global [%0], [%1], 16;" :: "r"(dst), "l"(src))
#define CP_COMMIT() asm volatile("cp.async.commit_group;" ::: "memory")
#define CP_WAIT0()  asm volatile("cp.async.wait_group 0;" ::: "memory")
#define CP_WAIT1()  asm volatile("cp.async.wait_group 1;" ::: "memory")

// ======================= small prep kernels =======================
__global__ void zero_out_kernel(float* p, int n) {
    int i = blockIdx.x * 1024 + threadIdx.x;
    if (i < n) p[i] = 0.f;
}

// x,sigmas [B][64][14] -> g_in0F [2][65][16][B]
__global__ void prep_input_kernel(const float* __restrict__ x,
                                  const float* __restrict__ sig) {
    int fk = blockIdx.x;            // 0..895
    int f = fk / 14, k = fk % 14;
    int t = threadIdx.x;
    for (int it = 0; it < 8; it++) {
        int b = it * 256 + t;
        float xv = x[(size_t)b * 896 + fk];
        float sv = sig[(size_t)b * 896 + fk] * 10.0f;
        g_in0F[((size_t)(0 * 65 + f + 1) * 16 + k + 1) * B_N + b] = xv;
        g_in0F[((size_t)(1 * 65 + f + 1) * 16 + k + 1) * B_N + b] = sv;
    }
}

// fp32 weights -> fp16 (single limb)
__global__ void cvt_w_kernel(const float* __restrict__ w, __half* __restrict__ o, int n) {
    int i = blockIdx.x * 256 + threadIdx.x;
    if (i >= n) return;
    o[i] = __float2half_rn(w[i]);
}

// ======================= conv1 (scalar fp32 -> fp16 CHWN) ===========
__global__ void __launch_bounds__(256, 2)
conv1_kernel(const float* __restrict__ w1,   // [64][2][3][3]
             const float* __restrict__ g1, const float* __restrict__ b1,
             const float* __restrict__ m1, const float* __restrict__ v1)
{
    __shared__ float sw[1152];
    const int w = blockIdx.x, h = blockIdx.y;
    const int t = threadIdx.x;
    for (int i = t; i < 1152; i += 256) sw[i] = w1[i];
    __syncthreads();

    const int b0 = (blockIdx.z * 256 + t) * 4;
    ull u[18][2];
    #pragma unroll
    for (int ci = 0; ci < 2; ci++)
        #pragma unroll
        for (int kh = 0; kh < 3; kh++)
            #pragma unroll
            for (int kw = 0; kw < 3; kw++) {
                int idx = ci * 9 + kh * 3 + kw;
                const ull* p = reinterpret_cast<const ull*>(
                    g_in0F + ((size_t)(ci * 65 + 2 * h + kh) * 16 + w + kw) * B_N + b0);
                u[idx][0] = p[0];
                u[idx][1] = p[1];
            }

    for (int co = 0; co < 64; co++) {
        ull a0 = 0ull, a1 = 0ull;
        #pragma unroll
        for (int idx = 0; idx < 18; idx++) {
            ull wv = pack2(sw[co * 18 + idx]);
            fma2(a0, u[idx][0], wv);
            fma2(a1, u[idx][1], wv);
        }
        float sc = __ldg(g1 + co) * rsqrtf(__ldg(v1 + co) + 1e-5f);
        float sh = __ldg(b1 + co) - __ldg(m1 + co) * sc;
        float2 p0 = unpack2(a0), p1 = unpack2(a1);
        float y0 = fmaxf(fmaf(p0.x, sc, sh), 0.f);
        float y1 = fmaxf(fmaf(p0.y, sc, sh), 0.f);
        float y2 = fmaxf(fmaf(p1.x, sc, sh), 0.f);
        float y3 = fmaxf(fmaf(p1.y, sc, sh), 0.f);
        size_t addr = ((size_t)(co * 34 + h + 1) * 16 + w + 1) * B_N + b0;
        *reinterpret_cast<uint32_t*>(g_a1 + addr)     = f16x2(y0, y1);
        *reinterpret_cast<uint32_t*>(g_a1 + addr + 2) = f16x2(y2, y3);
    }
}

// ======================= mma.sync conv GEMM v6 (fp16, single pass) =========
// CTA: D[128 co][128 n], K-chunk 32, 256 threads (8 warps, 4m x 2n).
// Weights fp16 single limb, activations fp16.  cp.async double-buffered.
// Grid: x = h (L2 reuse of X).  smem 38.9 KB -> 2 CTAs/SM.
// Per-buffer: A [128][40h] @0 (pitch 80B), B [32][136h] @10240 (pitch 272B).
static constexpr int OFF_B_L   = 10240;
static constexpr int BUF_SZ    = 18944;
static constexpr int OFF_PART  = 2 * BUF_SZ;        // 256 floats (FUSE4)
static constexpr int SMEM_TOT  = OFF_PART + 1024;   // 38912

template<int HPIN, int CHUNKS, bool FUSE4>
__global__ void __launch_bounds__(256, 2)
conv_mma(const __half* __restrict__ X,
         const __half* __restrict__ W,
         const float* __restrict__ gam, const float* __restrict__ bet,
         const float* __restrict__ mu,  const float* __restrict__ var,
         const float* __restrict__ w4,
         __half* __restrict__ O,
         float* __restrict__ dout, int HP_OUT)
{
    constexpr int KTOT = CHUNKS * 32;
    extern __shared__ __align__(16) char smem[];
    const uint32_t smb = smem_u32(smem);
    float* s_part = reinterpret_cast<float*>(smem + OFF_PART);

    const int tid  = threadIdx.x;
    const int lane = tid & 31, wid = tid >> 5;
    const int wm = wid & 3, wn = wid >> 2;          // 4m x 2n warps
    const int g = lane >> 2, t = lane & 3;
    const int h  = blockIdx.x;                      // h fastest => L2 reuse of X
    const int n0 = blockIdx.y * 128;
    const int mtile = blockIdx.z;
    const int w_pos = n0 >> 11;
    const int b0    = n0 & 2047;

    if (FUSE4) s_part[tid] = 0.f;

    // ldmatrix lane addresses (offsets within a buffer)
    const int rA = lane & 15;
    const int kA = (lane >> 4) << 3;
    const uint32_t aOff0 = (uint32_t)((wm * 32 +  0 + rA) * 80 + kA * 2);
    const uint32_t aOff1 = (uint32_t)((wm * 32 + 16 + rA) * 80 + kA * 2);
    const uint32_t bOff  = (uint32_t)(OFF_B_L + (lane & 15) * 272 + wn * 128);

    float acc[2][8][4];
    #pragma unroll
    for (int mt = 0; mt < 2; mt++)
        #pragma unroll
        for (int nt = 0; nt < 8; nt++)
            #pragma unroll
            for (int i = 0; i < 4; i++) acc[mt][nt][i] = 0.f;

    // ---- async stage of chunk cc into buffer bufOff ----
    auto stage = [&](int cc, uint32_t bufOff) {
        // A: weights [128co][32k] (64B data per row, pitch 80B)
        #pragma unroll
        for (int it = 0; it < 2; it++) {
            int e = it * 256 + tid;                 // 0..511
            int row = e >> 2, q = e & 3;
            size_t go = (size_t)(mtile * 128 + row) * KTOT + cc * 32 + q * 8;
            uint32_t so = smb + bufOff + (uint32_t)(row * 80 + q * 16);
            CP_ASYNC16(so, W + go);
        }
        // B: acts [32k][128n] fp16 (256B data per row, pitch 272B)
        #pragma unroll
        for (int it = 0; it < 2; it++) {
            int e = it * 256 + tid;                 // 0..511
            int row = e >> 4, n16 = e & 15;
            int k = cc * 32 + row;
            int ci = k / 9;
            int r9 = k - ci * 9;
            int kh = r9 / 3;
            int kw = r9 - kh * 3;
            size_t go = ((size_t)(ci * HPIN + 2 * h + kh) * 16 + w_pos + kw) * B_N
                        + b0 + n16 * 8;
            uint32_t so = smb + bufOff + (uint32_t)(OFF_B_L + row * 272 + n16 * 16);
            CP_ASYNC16(so, X + go);
        }
        CP_COMMIT();
    };

    stage(0, 0);

    #pragma unroll 1
    for (int c = 0; c < CHUNKS; c++) {
        const uint32_t cur = (c & 1) ? BUF_SZ : 0;
        if (c + 1 < CHUNKS) {
            stage(c + 1, cur ^ BUF_SZ);
            CP_WAIT1();
        } else {
            CP_WAIT0();
        }
        __syncthreads();

        const uint32_t aHi0 = smb + cur + aOff0;
        const uint32_t aHi1 = smb + cur + aOff1;
        const uint32_t bA   = smb + cur + bOff;
        #pragma unroll
        for (int ks = 0; ks < 2; ks++) {
            uint32_t Ah0[4], Ah1[4];
            ldsm4(Ah0, aHi0 + ks * 32);
            ldsm4(Ah1, aHi1 + ks * 32);
            #pragma unroll
            for (int nt = 0; nt < 8; nt++) {
                uint32_t bh[2];
                ldsm2t(bh, bA + ks * 4352 + nt * 16);
                mma16816(acc[0][nt], Ah0, bh);
                mma16816(acc[1][nt], Ah1, bh);
            }
        }
        __syncthreads();
    }

    // ======================= epilogue =======================
    const int co_base = mtile * 128 + wm * 32;
    if (!FUSE4) {
        #pragma unroll
        for (int mt = 0; mt < 2; mt++) {
            int co0 = co_base + mt * 16 + g, co1 = co0 + 8;
            float sc0 = gam[co0] * rsqrtf(var[co0] + 1e-5f);
            float sh0 = bet[co0] - mu[co0] * sc0;
            float sc1 = gam[co1] * rsqrtf(var[co1] + 1e-5f);
            float sh1 = bet[co1] - mu[co1] * sc1;
            size_t base0 = ((size_t)(co0 * HP_OUT + h + 1) * 16 + w_pos + 1) * B_N + b0;
            size_t base1 = ((size_t)(co1 * HP_OUT + h + 1) * 16 + w_pos + 1) * B_N + b0;
            #pragma unroll
            for (int nt = 0; nt < 8; nt++) {
                int nl = wn * 64 + nt * 8 + 2 * t;
                float y0 = fmaxf(fmaf(acc[mt][nt][0], sc0, sh0), 0.f);
                float y1 = fmaxf(fmaf(acc[mt][nt][1], sc0, sh0), 0.f);
                float y2 = fmaxf(fmaf(acc[mt][nt][2], sc1, sh1), 0.f);
                float y3 = fmaxf(fmaf(acc[mt][nt][3], sc1, sh1), 0.f);
                *reinterpret_cast<uint32_t*>(O + base0 + nl) = f16x2(y0, y1);
                *reinterpret_cast<uint32_t*>(O + base1 + nl) = f16x2(y2, y3);
            }
        }
    } else {
        float p0[16], p1[16];
        #pragma unroll
        for (int j = 0; j < 16; j++) { p0[j] = 0.f; p1[j] = 0.f; }
        #pragma unroll
        for (int mt = 0; mt < 2; mt++) {
            int co0 = co_base + mt * 16 + g, co1 = co0 + 8;
            float sc0 = gam[co0] * rsqrtf(var[co0] + 1e-5f);
            float sh0 = bet[co0] - mu[co0] * sc0;
            float sc1 = gam[co1] * rsqrtf(var[co1] + 1e-5f);
            float sh1 = bet[co1] - mu[co1] * sc1;
            float wa0 = w4[co0 * 8 + h], wb0 = w4[2048 + co0 * 8 + h];
            float wa1 = w4[co1 * 8 + h], wb1 = w4[2048 + co1 * 8 + h];
            #pragma unroll
            for (int nt = 0; nt < 8; nt++) {
                float y0 = fmaxf(fmaf(acc[mt][nt][0], sc0, sh0), 0.f);
                float y1 = fmaxf(fmaf(acc[mt][nt][1], sc0, sh0), 0.f);
                float y2 = fmaxf(fmaf(acc[mt][nt][2], sc1, sh1), 0.f);
                float y3 = fmaxf(fmaf(acc[mt][nt][3], sc1, sh1), 0.f);
                p0[nt * 2]     += y0 * wa0 + y2 * wa1;
                p0[nt * 2 + 1] += y1 * wa0 + y3 * wa1;
                p1[nt * 2]     += y0 * wb0 + y2 * wb1;
                p1[nt * 2 + 1] += y1 * wb0 + y3 * wb1;
            }
        }
        #pragma unroll
        for (int off = 4; off <= 16; off <<= 1) {
            #pragma unroll
            for (int j = 0; j < 16; j++) {
                p0[j] += __shfl_xor_sync(0xffffffffu, p0[j], off);
                p1[j] += __shfl_xor_sync(0xffffffffu, p1[j], off);
            }
        }
        if (g == 0) {
            #pragma unroll
            for (int j = 0; j < 16; j++) {
                int nl = wn * 64 + (j >> 1) * 8 + 2 * t + (j & 1);
                atomicAdd(&s_part[nl * 2],     p0[j]);
                atomicAdd(&s_part[nl * 2 + 1], p1[j]);
            }
        }
        __syncthreads();
        {
            int nl = tid >> 1, ch = tid & 1;
            atomicAdd(dout + (size_t)(b0 + nl) * 28 + w_pos * 2 + ch, s_part[tid]);
        }
    }
}

// ======================= host launch =======================
extern "C" void kernel_launch(void* const* d_in, const int* in_sizes, int n_in,
                              void* d_out, int out_size)
{
    (void)n_in;
    const float* x   = (const float*)d_in[0];
    const float* sig = (const float*)d_in[1];
    const float* w1  = (const float*)d_in[2];
    const float *w2, *w3, *w4;
    const float *g1,*b1,*m1,*v1,*g2,*b2,*m2,*v2,*g3,*b3,*m3,*v3;

    if (in_sizes[3] == 73728) {
        w2=(const float*)d_in[3];  w3=(const float*)d_in[4];  w4=(const float*)d_in[5];
        g1=(const float*)d_in[6];  b1=(const float*)d_in[7];  m1=(const float*)d_in[8];  v1=(const float*)d_in[9];
        g2=(const float*)d_in[10]; b2=(const float*)d_in[11]; m2=(const float*)d_in[12]; v2=(const float*)d_in[13];
        g3=(const float*)d_in[14]; b3=(const float*)d_in[15]; m3=(const float*)d_in[16]; v3=(const float*)d_in[17];
    } else {
        g1=(const float*)d_in[3];  b1=(const float*)d_in[4];  m1=(const float*)d_in[5];  v1=(const float*)d_in[6];
        w2=(const float*)d_in[7];
        g2=(const float*)d_in[8];  b2=(const float*)d_in[9];  m2=(const float*)d_in[10]; v2=(const float*)d_in[11];
        w3=(const float*)d_in[12];
        g3=(const float*)d_in[13]; b3=(const float*)d_in[14]; m3=(const float*)d_in[15]; v3=(const float*)d_in[16];
        w4=(const float*)d_in[17];
    }

    __half *a1, *a2, *w2h, *w3h;
    cudaGetSymbolAddress((void**)&a1, g_a1);
    cudaGetSymbolAddress((void**)&a2, g_a2);
    cudaGetSymbolAddress((void**)&w2h, g_w2);
    cudaGetSymbolAddress((void**)&w3h, g_w3);

    cudaFuncSetAttribute(conv_mma<34, 18, false>,
                         cudaFuncAttributeMaxDynamicSharedMemorySize, SMEM_TOT);
    cudaFuncSetAttribute(conv_mma<18, 36, true>,
                         cudaFuncAttributeMaxDynamicSharedMemorySize, SMEM_TOT);

    // 0) zero output accumulator (conv4 adds atomically)
    zero_out_kernel<<<(out_size + 1023) / 1024, 1024>>>((float*)d_out, out_size);
    // 1) input -> padded fp32 CHWN
    prep_input_kernel<<<896, 256>>>(x, sig);
    // 2) weights -> fp16
    cvt_w_kernel<<<(73728 + 255) / 256, 256>>>(w2, w2h, 73728);
    cvt_w_kernel<<<(294912 + 255) / 256, 256>>>(w3, w3h, 294912);
    // 3) conv1 scalar -> a1 (fp16 CHWN)
    conv1_kernel<<<dim3(14, 32, 2), 256>>>(w1, g1, b1, m1, v1);
    // 4) conv2 (fp16 single-pass mma, pipelined) -> a2
    conv_mma<34, 18, false><<<dim3(16, 224, 1), 256, SMEM_TOT>>>(
        a1, w2h, g2, b2, m2, v2, nullptr, a2, nullptr, 18);
    // 5) conv3 (fp16 single-pass mma) + fused conv4 -> d_out
    conv_mma<18, 36, true><<<dim3(8, 224, 2), 256, SMEM_TOT>>>(
        a2, w3h, g3, b3, m3, v3, w4, nullptr, (float*)d_out, 0);
}

// round 12
// speedup vs baseline: 9.4447x; 1.1539x over previous
#include <cuda_runtime.h>
#include <cuda_fp16.h>
#include <cstdint>

typedef unsigned long long ull;

#define B_N 2048

// ---------------- device scratch (zero-init at load; pad cells never written) ----
__device__ float  g_in0F[2 * 65 * 16 * 2048];                // conv1 input, padded CHWN
__device__ __half g_a1[(size_t)64 * 34 * 16 * 2048];         // conv1 out (fp16)
__device__ __half g_a2[(size_t)128 * 18 * 16 * 2048];        // conv2 out (fp16)
__device__ __half g_w2[128 * 576];
__device__ __half g_w3[256 * 1152];

// ---------------- helpers ----------------
__device__ __forceinline__ uint32_t smem_u32(const void* p) {
    uint32_t a;
    asm("{ .reg .u64 t; cvta.to.shared.u64 t, %1; cvt.u32.u64 %0, t; }"
        : "=r"(a) : "l"(p));
    return a;
}
__device__ __forceinline__ ull pack2(float x) {
    ull r; asm("mov.b64 %0, {%1, %1};" : "=l"(r) : "f"(x)); return r;
}
__device__ __forceinline__ void fma2(ull &acc, ull a, ull b) {
    asm("fma.rn.f32x2 %0, %1, %2, %0;" : "+l"(acc) : "l"(a), "l"(b));
}
__device__ __forceinline__ float2 unpack2(ull v) {
    float2 r; asm("mov.b64 {%0, %1}, %2;" : "=f"(r.x), "=f"(r.y) : "l"(v)); return r;
}
__device__ __forceinline__ uint32_t f16x2(float y0, float y1) {
    __half2 h = __floats2half2_rn(y0, y1);      // y0 -> low half
    return *reinterpret_cast<uint32_t*>(&h);
}

// ldmatrix / mma.sync (base ISA)
__device__ __forceinline__ void ldsm4(uint32_t* r, uint32_t a) {
    asm volatile("ldmatrix.sync.aligned.m8n8.x4.shared.b16 {%0,%1,%2,%3}, [%4];"
        : "=r"(r[0]), "=r"(r[1]), "=r"(r[2]), "=r"(r[3]) : "r"(a));
}
__device__ __forceinline__ void ldsm4t(uint32_t* r, uint32_t a) {
    asm volatile("ldmatrix.sync.aligned.m8n8.x4.trans.shared.b16 {%0,%1,%2,%3}, [%4];"
        : "=r"(r[0]), "=r"(r[1]), "=r"(r[2]), "=r"(r[3]) : "r"(a));
}
__device__ __forceinline__ void mma16816(float* d, const uint32_t* a, const uint32_t* b) {
    asm volatile(
        "mma.sync.aligned.m16n8k16.row.col.f32.f16.f16.f32 "
        "{%0,%1,%2,%3}, {%4,%5,%6,%7}, {%8,%9}, {%0,%1,%2,%3};"
        : "+f"(d[0]), "+f"(d[1]), "+f"(d[2]), "+f"(d[3])
        : "r"(a[0]), "r"(a[1]), "r"(a[2]), "r"(a[3]), "r"(b[0]), "r"(b[1]));
}

// cp.async
#define CP_ASYNC16(dst, src) \
    asm volatile("cp.async.cg.shared.global [%0], [%1], 16;" :: "r"(dst), "l"(src))
#define CP_COMMIT() asm volatile("cp.async.commit_group;" ::: "memory")
#define CP_WAIT0()  asm volatile("cp.async.wait_group 0;" ::: "memory")
#define CP_WAIT1()  asm volatile("cp.async.wait_group 1;" ::: "memory")

// ======================= small prep kernels =======================
__global__ void zero_out_kernel(float* p, int n) {
    int i = blockIdx.x * 1024 + threadIdx.x;
    if (i < n) p[i] = 0.f;
}

// x,sigmas [B][64][14] -> g_in0F [2][65][16][B]
__global__ void prep_input_kernel(const float* __restrict__ x,
                                  const float* __restrict__ sig) {
    int fk = blockIdx.x;            // 0..895
    int f = fk / 14, k = fk % 14;
    int t = threadIdx.x;
    for (int it = 0; it < 8; it++) {
        int b = it * 256 + t;
        float xv = x[(size_t)b * 896 + fk];
        float sv = sig[(size_t)b * 896 + fk] * 10.0f;
        g_in0F[((size_t)(0 * 65 + f + 1) * 16 + k + 1) * B_N + b] = xv;
        g_in0F[((size_t)(1 * 65 + f + 1) * 16 + k + 1) * B_N + b] = sv;
    }
}

// fp32 weights -> fp16 (single limb)
__global__ void cvt_w_kernel(const float* __restrict__ w, __half* __restrict__ o, int n) {
    int i = blockIdx.x * 256 + threadIdx.x;
    if (i >= n) return;
    o[i] = __float2half_rn(w[i]);
}

// ======================= conv1 (scalar fp32 -> fp16 CHWN) ===========
__global__ void __launch_bounds__(256, 2)
conv1_kernel(const float* __restrict__ w1,   // [64][2][3][3]
             const float* __restrict__ g1, const float* __restrict__ b1,
             const float* __restrict__ m1, const float* __restrict__ v1)
{
    __shared__ float sw[1152];
    const int w = blockIdx.x, h = blockIdx.y;
    const int t = threadIdx.x;
    for (int i = t; i < 1152; i += 256) sw[i] = w1[i];
    __syncthreads();

    const int b0 = (blockIdx.z * 256 + t) * 4;
    ull u[18][2];
    #pragma unroll
    for (int ci = 0; ci < 2; ci++)
        #pragma unroll
        for (int kh = 0; kh < 3; kh++)
            #pragma unroll
            for (int kw = 0; kw < 3; kw++) {
                int idx = ci * 9 + kh * 3 + kw;
                const ull* p = reinterpret_cast<const ull*>(
                    g_in0F + ((size_t)(ci * 65 + 2 * h + kh) * 16 + w + kw) * B_N + b0);
                u[idx][0] = p[0];
                u[idx][1] = p[1];
            }

    for (int co = 0; co < 64; co++) {
        ull a0 = 0ull, a1 = 0ull;
        #pragma unroll
        for (int idx = 0; idx < 18; idx++) {
            ull wv = pack2(sw[co * 18 + idx]);
            fma2(a0, u[idx][0], wv);
            fma2(a1, u[idx][1], wv);
        }
        float sc = __ldg(g1 + co) * rsqrtf(__ldg(v1 + co) + 1e-5f);
        float sh = __ldg(b1 + co) - __ldg(m1 + co) * sc;
        float2 p0 = unpack2(a0), p1 = unpack2(a1);
        float y0 = fmaxf(fmaf(p0.x, sc, sh), 0.f);
        float y1 = fmaxf(fmaf(p0.y, sc, sh), 0.f);
        float y2 = fmaxf(fmaf(p1.x, sc, sh), 0.f);
        float y3 = fmaxf(fmaf(p1.y, sc, sh), 0.f);
        size_t addr = ((size_t)(co * 34 + h + 1) * 16 + w + 1) * B_N + b0;
        *reinterpret_cast<uint32_t*>(g_a1 + addr)     = f16x2(y0, y1);
        *reinterpret_cast<uint32_t*>(g_a1 + addr + 2) = f16x2(y2, y3);
    }
}

// ======================= mma.sync conv GEMM v7 (fp16, K-chunk 64) ==========
// CTA: D[128 co][128 n], K-chunk 64, 256 threads (8 warps, 4m x 2n).
// Weights fp16, activations fp16, single pass.  cp.async double-buffered.
// Grid: x = h (L2 reuse of X).  smem 72.7 KB -> 2 CTAs/SM.
// Per-buffer: A [128][72h] @0 (pitch 144B), B [64][136h] @18432 (pitch 272B).
static constexpr int OFF_B_L   = 18432;
static constexpr int BUF_SZ    = 35840;
static constexpr int OFF_PART  = 2 * BUF_SZ;        // 256 floats (FUSE4)
static constexpr int SMEM_TOT  = OFF_PART + 1024;   // 72704

template<int HPIN, int CHUNKS, bool FUSE4>
__global__ void __launch_bounds__(256, 2)
conv_mma(const __half* __restrict__ X,
         const __half* __restrict__ W,
         const float* __restrict__ gam, const float* __restrict__ bet,
         const float* __restrict__ mu,  const float* __restrict__ var,
         const float* __restrict__ w4,
         __half* __restrict__ O,
         float* __restrict__ dout, int HP_OUT)
{
    constexpr int KTOT = CHUNKS * 64;
    extern __shared__ __align__(16) char smem[];
    const uint32_t smb = smem_u32(smem);
    float* s_part = reinterpret_cast<float*>(smem + OFF_PART);

    const int tid  = threadIdx.x;
    const int lane = tid & 31, wid = tid >> 5;
    const int wm = wid & 3, wn = wid >> 2;          // 4m x 2n warps
    const int g = lane >> 2, t = lane & 3;
    const int h  = blockIdx.x;                      // h fastest => L2 reuse of X
    const int n0 = blockIdx.y * 128;
    const int mtile = blockIdx.z;
    const int w_pos = n0 >> 11;
    const int b0    = n0 & 2047;

    if (FUSE4) s_part[tid] = 0.f;

    // ldmatrix lane addresses (offsets within a buffer)
    const int rA = lane & 15;
    const int kA = (lane >> 4) << 3;
    const uint32_t aOff0 = (uint32_t)((wm * 32 +  0 + rA) * 144 + kA * 2);
    const uint32_t aOff1 = (uint32_t)((wm * 32 + 16 + rA) * 144 + kA * 2);
    // B x4-trans: lanes 0-15 -> k rows at n-base, lanes 16-31 -> same rows, n+8
    const uint32_t bOff  = (uint32_t)(OFF_B_L + (lane & 15) * 272
                                      + (lane >> 4) * 16 + wn * 128);

    float acc[2][8][4];
    #pragma unroll
    for (int mt = 0; mt < 2; mt++)
        #pragma unroll
        for (int nt = 0; nt < 8; nt++)
            #pragma unroll
            for (int i = 0; i < 4; i++) acc[mt][nt][i] = 0.f;

    // ---- async stage of chunk cc into buffer bufOff ----
    auto stage = [&](int cc, uint32_t bufOff) {
        // A: weights [128co][64k] (128B data per row, pitch 144B)
        #pragma unroll
        for (int it = 0; it < 4; it++) {
            int e = it * 256 + tid;                 // 0..1023
            int row = e >> 3, q = e & 7;
            size_t go = (size_t)(mtile * 128 + row) * KTOT + cc * 64 + q * 8;
            uint32_t so = smb + bufOff + (uint32_t)(row * 144 + q * 16);
            CP_ASYNC16(so, W + go);
        }
        // B: acts [64k][128n] fp16 (256B data per row, pitch 272B)
        #pragma unroll
        for (int it = 0; it < 4; it++) {
            int e = it * 256 + tid;                 // 0..1023
            int row = e >> 4, n16 = e & 15;
            int k = cc * 64 + row;
            int ci = k / 9;
            int r9 = k - ci * 9;
            int kh = r9 / 3;
            int kw = r9 - kh * 3;
            size_t go = ((size_t)(ci * HPIN + 2 * h + kh) * 16 + w_pos + kw) * B_N
                        + b0 + n16 * 8;
            uint32_t so = smb + bufOff + (uint32_t)(OFF_B_L + row * 272 + n16 * 16);
            CP_ASYNC16(so, X + go);
        }
        CP_COMMIT();
    };

    stage(0, 0);

    #pragma unroll 1
    for (int c = 0; c < CHUNKS; c++) {
        const uint32_t cur = (c & 1) ? BUF_SZ : 0;
        if (c + 1 < CHUNKS) {
            stage(c + 1, cur ^ BUF_SZ);
            CP_WAIT1();
        } else {
            CP_WAIT0();
        }
        __syncthreads();

        const uint32_t aHi0 = smb + cur + aOff0;
        const uint32_t aHi1 = smb + cur + aOff1;
        const uint32_t bA   = smb + cur + bOff;
        #pragma unroll
        for (int ks = 0; ks < 4; ks++) {
            uint32_t Ah0[4], Ah1[4];
            ldsm4(Ah0, aHi0 + ks * 32);
            ldsm4(Ah1, aHi1 + ks * 32);
            #pragma unroll
            for (int ntp = 0; ntp < 4; ntp++) {     // nt pairs
                uint32_t bf[4];
                ldsm4t(bf, bA + ks * (16 * 272) + ntp * 32);
                mma16816(acc[0][2 * ntp],     Ah0, bf);
                mma16816(acc[1][2 * ntp],     Ah1, bf);
                mma16816(acc[0][2 * ntp + 1], Ah0, bf + 2);
                mma16816(acc[1][2 * ntp + 1], Ah1, bf + 2);
            }
        }
        __syncthreads();
    }

    // ======================= epilogue =======================
    const int co_base = mtile * 128 + wm * 32;
    if (!FUSE4) {
        #pragma unroll
        for (int mt = 0; mt < 2; mt++) {
            int co0 = co_base + mt * 16 + g, co1 = co0 + 8;
            float sc0 = gam[co0] * rsqrtf(var[co0] + 1e-5f);
            float sh0 = bet[co0] - mu[co0] * sc0;
            float sc1 = gam[co1] * rsqrtf(var[co1] + 1e-5f);
            float sh1 = bet[co1] - mu[co1] * sc1;
            size_t base0 = ((size_t)(co0 * HP_OUT + h + 1) * 16 + w_pos + 1) * B_N + b0;
            size_t base1 = ((size_t)(co1 * HP_OUT + h + 1) * 16 + w_pos + 1) * B_N + b0;
            #pragma unroll
            for (int nt = 0; nt < 8; nt++) {
                int nl = wn * 64 + nt * 8 + 2 * t;
                float y0 = fmaxf(fmaf(acc[mt][nt][0], sc0, sh0), 0.f);
                float y1 = fmaxf(fmaf(acc[mt][nt][1], sc0, sh0), 0.f);
                float y2 = fmaxf(fmaf(acc[mt][nt][2], sc1, sh1), 0.f);
                float y3 = fmaxf(fmaf(acc[mt][nt][3], sc1, sh1), 0.f);
                *reinterpret_cast<uint32_t*>(O + base0 + nl) = f16x2(y0, y1);
                *reinterpret_cast<uint32_t*>(O + base1 + nl) = f16x2(y2, y3);
            }
        }
    } else {
        float p0[16], p1[16];
        #pragma unroll
        for (int j = 0; j < 16; j++) { p0[j] = 0.f; p1[j] = 0.f; }
        #pragma unroll
        for (int mt = 0; mt < 2; mt++) {
            int co0 = co_base + mt * 16 + g, co1 = co0 + 8;
            float sc0 = gam[co0] * rsqrtf(var[co0] + 1e-5f);
            float sh0 = bet[co0] - mu[co0] * sc0;
            float sc1 = gam[co1] * rsqrtf(var[co1] + 1e-5f);
            float sh1 = bet[co1] - mu[co1] * sc1;
            float wa0 = w4[co0 * 8 + h], wb0 = w4[2048 + co0 * 8 + h];
            float wa1 = w4[co1 * 8 + h], wb1 = w4[2048 + co1 * 8 + h];
            #pragma unroll
            for (int nt = 0; nt < 8; nt++) {
                float y0 = fmaxf(fmaf(acc[mt][nt][0], sc0, sh0), 0.f);
                float y1 = fmaxf(fmaf(acc[mt][nt][1], sc0, sh0), 0.f);
                float y2 = fmaxf(fmaf(acc[mt][nt][2], sc1, sh1), 0.f);
                float y3 = fmaxf(fmaf(acc[mt][nt][3], sc1, sh1), 0.f);
                p0[nt * 2]     += y0 * wa0 + y2 * wa1;
                p0[nt * 2 + 1] += y1 * wa0 + y3 * wa1;
                p1[nt * 2]     += y0 * wb0 + y2 * wb1;
                p1[nt * 2 + 1] += y1 * wb0 + y3 * wb1;
            }
        }
        #pragma unroll
        for (int off = 4; off <= 16; off <<= 1) {
            #pragma unroll
            for (int j = 0; j < 16; j++) {
                p0[j] += __shfl_xor_sync(0xffffffffu, p0[j], off);
                p1[j] += __shfl_xor_sync(0xffffffffu, p1[j], off);
            }
        }
        if (g == 0) {
            #pragma unroll
            for (int j = 0; j < 16; j++) {
                int nl = wn * 64 + (j >> 1) * 8 + 2 * t + (j & 1);
                atomicAdd(&s_part[nl * 2],     p0[j]);
                atomicAdd(&s_part[nl * 2 + 1], p1[j]);
            }
        }
        __syncthreads();
        {
            int nl = tid >> 1, ch = tid & 1;
            atomicAdd(dout + (size_t)(b0 + nl) * 28 + w_pos * 2 + ch, s_part[tid]);
        }
    }
}

// ======================= host launch =======================
extern "C" void kernel_launch(void* const* d_in, const int* in_sizes, int n_in,
                              void* d_out, int out_size)
{
    (void)n_in;
    const float* x   = (const float*)d_in[0];
    const float* sig = (const float*)d_in[1];
    const float* w1  = (const float*)d_in[2];
    const float *w2, *w3, *w4;
    const float *g1,*b1,*m1,*v1,*g2,*b2,*m2,*v2,*g3,*b3,*m3,*v3;

    if (in_sizes[3] == 73728) {
        w2=(const float*)d_in[3];  w3=(const float*)d_in[4];  w4=(const float*)d_in[5];
        g1=(const float*)d_in[6];  b1=(const float*)d_in[7];  m1=(const float*)d_in[8];  v1=(const float*)d_in[9];
        g2=(const float*)d_in[10]; b2=(const float*)d_in[11]; m2=(const float*)d_in[12]; v2=(const float*)d_in[13];
        g3=(const float*)d_in[14]; b3=(const float*)d_in[15]; m3=(const float*)d_in[16]; v3=(const float*)d_in[17];
    } else {
        g1=(const float*)d_in[3];  b1=(const float*)d_in[4];  m1=(const float*)d_in[5];  v1=(const float*)d_in[6];
        w2=(const float*)d_in[7];
        g2=(const float*)d_in[8];  b2=(const float*)d_in[9];  m2=(const float*)d_in[10]; v2=(const float*)d_in[11];
        w3=(const float*)d_in[12];
        g3=(const float*)d_in[13]; b3=(const float*)d_in[14]; m3=(const float*)d_in[15]; v3=(const float*)d_in[16];
        w4=(const float*)d_in[17];
    }

    __half *a1, *a2, *w2h, *w3h;
    cudaGetSymbolAddress((void**)&a1, g_a1);
    cudaGetSymbolAddress((void**)&a2, g_a2);
    cudaGetSymbolAddress((void**)&w2h, g_w2);
    cudaGetSymbolAddress((void**)&w3h, g_w3);

    cudaFuncSetAttribute(conv_mma<34, 9, false>,
                         cudaFuncAttributeMaxDynamicSharedMemorySize, SMEM_TOT);
    cudaFuncSetAttribute(conv_mma<18, 18, true>,
                         cudaFuncAttributeMaxDynamicSharedMemorySize, SMEM_TOT);

    // 0) zero output accumulator (conv4 adds atomically)
    zero_out_kernel<<<(out_size + 1023) / 1024, 1024>>>((float*)d_out, out_size);
    // 1) input -> padded fp32 CHWN
    prep_input_kernel<<<896, 256>>>(x, sig);
    // 2) weights -> fp16
    cvt_w_kernel<<<(73728 + 255) / 256, 256>>>(w2, w2h, 73728);
    cvt_w_kernel<<<(294912 + 255) / 256, 256>>>(w3, w3h, 294912);
    // 3) conv1 scalar -> a1 (fp16 CHWN)
    conv1_kernel<<<dim3(14, 32, 2), 256>>>(w1, g1, b1, m1, v1);
    // 4) conv2 (fp16 mma, K-chunk 64, pipelined) -> a2
    conv_mma<34, 9, false><<<dim3(16, 224, 1), 256, SMEM_TOT>>>(
        a1, w2h, g2, b2, m2, v2, nullptr, a2, nullptr, 18);
    // 5) conv3 (fp16 mma, K-chunk 64) + fused conv4 -> d_out
    conv_mma<18, 18, true><<<dim3(8, 224, 2), 256, SMEM_TOT>>>(
        a2, w3h, g3, b3, m3, v3, w4, nullptr, (float*)d_out, 0);
}